// round 1
// baseline (speedup 1.0000x reference)
#include <cuda_runtime.h>
#include <cuda_bf16.h>
#include <math.h>

// Problem constants (fixed shapes per reference)
#define N_NODES 100000
#define IN_DIM  64
#define HID     32
#define N_EDGES 1600000
#define N_REL   3
#define N_GRAPH 256

// ---------------- device scratch (no allocations allowed) ----------------
__device__ float g_rel[(size_t)N_REL * N_NODES * HID];   // [r][n][32]
__device__ float g_aggA[N_NODES * HID];
__device__ float g_aggB[N_NODES * HID];
__device__ float g_s0[N_NODES * HID];
__device__ float g_s1[N_NODES * HID];
__device__ float g_s2[N_NODES * HID];
__device__ int   g_deg[N_NODES];
__device__ int   g_cur[N_NODES];
__device__ int   g_rowptr[N_NODES + 1];
__device__ int   g_edge_packed[N_EDGES];                  // src | (etype<<17)
__device__ float g_W1[3 * IN_DIM * HID];                  // layer-1 relation weights
__device__ float g_Wr[9 * HID * HID];                     // layers 2-4 relation weights
__device__ float g_pooled[N_GRAPH * 128];
__device__ int   g_cnt[N_GRAPH];

// ---------------- kernels ----------------

__global__ void zero_kernel() {
    int i = blockIdx.x * blockDim.x + threadIdx.x;
    int stride = gridDim.x * blockDim.x;
    for (int j = i; j < N_NODES; j += stride) { g_deg[j] = 0; g_cur[j] = 0; }
    for (int j = i; j < N_GRAPH * 128; j += stride) g_pooled[j] = 0.0f;
    for (int j = i; j < N_GRAPH; j += stride) g_cnt[j] = 0;
}

// W[l][r] = sum_b w_comp[l,r,b] * basis[b]
__global__ void computeW_kernel(const float* __restrict__ basis1,
                                const float* __restrict__ basis_r,
                                const float* __restrict__ wcomp) {
    int i = blockIdx.x * blockDim.x + threadIdx.x;
    if (i < 3 * IN_DIM * HID) {
        int r = i / (IN_DIM * HID);
        int io = i % (IN_DIM * HID);
        g_W1[i] = wcomp[(0 * 3 + r) * 2 + 0] * basis1[0 * IN_DIM * HID + io]
                + wcomp[(0 * 3 + r) * 2 + 1] * basis1[1 * IN_DIM * HID + io];
    }
    int j = i - 3 * IN_DIM * HID;
    if (j >= 0 && j < 9 * HID * HID) {
        int l  = j / (3 * HID * HID);          // 0..2  (conv layers 2..4)
        int rem = j % (3 * HID * HID);
        int r  = rem / (HID * HID);
        int io = rem % (HID * HID);
        g_Wr[j] = wcomp[((l + 1) * 3 + r) * 2 + 0] * basis_r[(l * 2 + 0) * HID * HID + io]
                + wcomp[((l + 1) * 3 + r) * 2 + 1] * basis_r[(l * 2 + 1) * HID * HID + io];
    }
}

__global__ void hist_kernel(const int* __restrict__ dst) {
    int i = blockIdx.x * blockDim.x + threadIdx.x;
    int stride = gridDim.x * blockDim.x;
    for (int e = i; e < N_EDGES; e += stride) atomicAdd(&g_deg[dst[e]], 1);
}

// single-block exclusive scan of g_deg -> g_rowptr
__global__ void scan_kernel() {
    __shared__ int wsum[32];
    __shared__ int s_carry;
    int tid = threadIdx.x, lane = tid & 31, wid = tid >> 5;
    if (tid == 0) s_carry = 0;
    __syncthreads();
    for (int base = 0; base < N_NODES; base += 1024) {
        int i = base + tid;
        int v = (i < N_NODES) ? g_deg[i] : 0;
        int x = v;
        #pragma unroll
        for (int o = 1; o < 32; o <<= 1) {
            int t = __shfl_up_sync(0xffffffffu, x, o);
            if (lane >= o) x += t;
        }
        if (lane == 31) wsum[wid] = x;
        __syncthreads();
        if (wid == 0) {
            int s = wsum[lane];
            #pragma unroll
            for (int o = 1; o < 32; o <<= 1) {
                int t = __shfl_up_sync(0xffffffffu, s, o);
                if (lane >= o) s += t;
            }
            wsum[lane] = s;
        }
        __syncthreads();
        int pre = (wid > 0) ? wsum[wid - 1] : 0;
        int excl = s_carry + pre + (x - v);
        if (i < N_NODES) g_rowptr[i] = excl;
        int chunk_total = wsum[31];
        __syncthreads();
        if (tid == 0) s_carry += chunk_total;
        __syncthreads();
    }
    if (tid == 0) g_rowptr[N_NODES] = s_carry;
}

__global__ void scatter_kernel(const int* __restrict__ src,
                               const int* __restrict__ dst,
                               const int* __restrict__ etype) {
    int i = blockIdx.x * blockDim.x + threadIdx.x;
    int stride = gridDim.x * blockDim.x;
    for (int e = i; e < N_EDGES; e += stride) {
        int d = dst[e];
        int p = g_rowptr[d] + atomicAdd(&g_cur[d], 1);
        g_edge_packed[p] = src[e] | (etype[e] << 17);
    }
}

// Layer 1 dense: warp per node. rel[r][n] = x[n] @ W1[r]; agg = x[n]@loop1 + bias0
__global__ void dense0_kernel(const float* __restrict__ x,
                              const float* __restrict__ loop1,
                              const float* __restrict__ bias) {
    __shared__ float sW[4 * IN_DIM * HID];   // 32KB: rel0,rel1,rel2,loop
    int tid = threadIdx.x;
    for (int i = tid; i < 4 * IN_DIM * HID; i += 256)
        sW[i] = (i < 3 * IN_DIM * HID) ? g_W1[i] : loop1[i - 3 * IN_DIM * HID];
    __syncthreads();
    int lane = tid & 31, w = tid >> 5;
    int n = blockIdx.x * 8 + w;
    if (n >= N_NODES) return;
    float h0 = x[n * IN_DIM + lane];
    float h1 = x[n * IN_DIM + 32 + lane];
    float a0 = 0.f, a1 = 0.f, a2 = 0.f, aL = 0.f;
    #pragma unroll
    for (int i = 0; i < 32; i++) {
        float hv = __shfl_sync(0xffffffffu, h0, i);
        a0 += hv * sW[0 * 2048 + i * 32 + lane];
        a1 += hv * sW[1 * 2048 + i * 32 + lane];
        a2 += hv * sW[2 * 2048 + i * 32 + lane];
        aL += hv * sW[3 * 2048 + i * 32 + lane];
    }
    #pragma unroll
    for (int i = 0; i < 32; i++) {
        float hv = __shfl_sync(0xffffffffu, h1, i);
        int ii = 32 + i;
        a0 += hv * sW[0 * 2048 + ii * 32 + lane];
        a1 += hv * sW[1 * 2048 + ii * 32 + lane];
        a2 += hv * sW[2 * 2048 + ii * 32 + lane];
        aL += hv * sW[3 * 2048 + ii * 32 + lane];
    }
    g_rel[((size_t)0 * N_NODES + n) * HID + lane] = a0;
    g_rel[((size_t)1 * N_NODES + n) * HID + lane] = a1;
    g_rel[((size_t)2 * N_NODES + n) * HID + lane] = a2;
    g_aggA[n * HID + lane] = aL + bias[lane];   // bias row 0
}

// Layers 2-4 dense: h = tanh(aggIn); store state; rel & self-loop init for next agg
__global__ void denseR_kernel(const float* __restrict__ aggIn,
                              float* __restrict__ stateOut,
                              float* __restrict__ aggOut,
                              int wOffset,
                              const float* __restrict__ loopW,
                              const float* __restrict__ biasRow) {
    __shared__ float sW[4 * HID * HID];   // 16KB
    int tid = threadIdx.x;
    for (int i = tid; i < 4 * HID * HID; i += 256)
        sW[i] = (i < 3 * HID * HID) ? g_Wr[wOffset + i] : loopW[i - 3 * HID * HID];
    __syncthreads();
    int lane = tid & 31, w = tid >> 5;
    int n = blockIdx.x * 8 + w;
    if (n >= N_NODES) return;
    float h = tanhf(aggIn[n * HID + lane]);
    stateOut[n * HID + lane] = h;
    float a0 = 0.f, a1 = 0.f, a2 = 0.f, aL = 0.f;
    #pragma unroll
    for (int i = 0; i < 32; i++) {
        float hv = __shfl_sync(0xffffffffu, h, i);
        a0 += hv * sW[0 * 1024 + i * 32 + lane];
        a1 += hv * sW[1 * 1024 + i * 32 + lane];
        a2 += hv * sW[2 * 1024 + i * 32 + lane];
        aL += hv * sW[3 * 1024 + i * 32 + lane];
    }
    g_rel[((size_t)0 * N_NODES + n) * HID + lane] = a0;
    g_rel[((size_t)1 * N_NODES + n) * HID + lane] = a1;
    g_rel[((size_t)2 * N_NODES + n) * HID + lane] = a2;
    aggOut[n * HID + lane] = aL + biasRow[lane];
}

// Pull aggregation: warp per dst node, no atomics
__global__ void pull_kernel(float* __restrict__ agg) {
    int gw = (blockIdx.x * blockDim.x + threadIdx.x) >> 5;
    int lane = threadIdx.x & 31;
    if (gw >= N_NODES) return;
    int row = g_rowptr[gw], end = g_rowptr[gw + 1];
    float acc = agg[gw * HID + lane];
    int k = row;
    for (; k + 1 < end; k += 2) {
        int p0 = __ldg(&g_edge_packed[k]);
        int p1 = __ldg(&g_edge_packed[k + 1]);
        int s0 = p0 & 0x1FFFF, r0 = p0 >> 17;
        int s1 = p1 & 0x1FFFF, r1 = p1 >> 17;
        float v0 = g_rel[((size_t)r0 * N_NODES + s0) * HID + lane];
        float v1 = g_rel[((size_t)r1 * N_NODES + s1) * HID + lane];
        acc += v0;
        acc += v1;
    }
    if (k < end) {
        int p0 = __ldg(&g_edge_packed[k]);
        int s0 = p0 & 0x1FFFF, r0 = p0 >> 17;
        acc += g_rel[((size_t)r0 * N_NODES + s0) * HID + lane];
    }
    agg[gw * HID + lane] = acc;
}

// Mean-pool over sorted graph_ids: run-length accumulate, few atomics
#define POOL_NODES 256
__global__ void pool_kernel(const int* __restrict__ gids) {
    __shared__ int sg[POOL_NODES];
    int f = threadIdx.x;             // 128 threads: one feature each
    int base = blockIdx.x * POOL_NODES;
    for (int j = f; j < POOL_NODES; j += 128) {
        int n = base + j;
        sg[j] = (n < N_NODES) ? gids[n] : -1;
    }
    __syncthreads();
    int nn = N_NODES - base;
    if (nn > POOL_NODES) nn = POOL_NODES;
    float acc = 0.f; int curg = -1; int run = 0;
    for (int j = 0; j < nn; j++) {
        int n = base + j;
        float v;
        if (f < 32)       v = g_s0[n * HID + f];
        else if (f < 64)  v = g_s1[n * HID + (f - 32)];
        else if (f < 96)  v = g_s2[n * HID + (f - 64)];
        else              v = tanhf(g_aggB[n * HID + (f - 96)]);
        int g = sg[j];
        if (g != curg) {
            if (curg >= 0) {
                atomicAdd(&g_pooled[curg * 128 + f], acc);
                if (f == 0) atomicAdd(&g_cnt[curg], run);
            }
            curg = g; acc = 0.f; run = 0;
        }
        acc += v; run++;
    }
    if (curg >= 0) {
        atomicAdd(&g_pooled[curg * 128 + f], acc);
        if (f == 0) atomicAdd(&g_cnt[curg], run);
    }
}

// Final MLP: one block per graph, 64 threads
__global__ void mlp_kernel(const float* __restrict__ lin1_w,
                           const float* __restrict__ lin1_b,
                           const float* __restrict__ lin2_w,
                           const float* __restrict__ lin2_b,
                           float* __restrict__ out) {
    int g = blockIdx.x;
    int k = threadIdx.x;             // 0..63
    __shared__ float sp[128];
    __shared__ float partial[2];
    float cnt = (float)g_cnt[g];
    float inv = 1.0f / fmaxf(cnt, 1.0f);
    sp[k]      = g_pooled[g * 128 + k] * inv;
    sp[64 + k] = g_pooled[g * 128 + 64 + k] * inv;
    __syncthreads();
    float acc = lin1_b[k];
    #pragma unroll
    for (int j = 0; j < 128; j++) acc += sp[j] * lin1_w[j * 64 + k];
    float h = fmaxf(acc, 0.0f);
    float t = h * lin2_w[k];
    #pragma unroll
    for (int o = 16; o > 0; o >>= 1) t += __shfl_down_sync(0xffffffffu, t, o);
    if ((k & 31) == 0) partial[k >> 5] = t;
    __syncthreads();
    if (k == 0) {
        float s = partial[0] + partial[1] + lin2_b[0];
        out[g] = 1.0f / (1.0f + expf(-s));
    }
}

// ---------------- launcher ----------------
extern "C" void kernel_launch(void* const* d_in, const int* in_sizes, int n_in,
                              void* d_out, int out_size) {
    const float* x       = (const float*)d_in[0];
    const float* basis1  = (const float*)d_in[1];
    const float* basis_r = (const float*)d_in[2];
    const float* w_comp  = (const float*)d_in[3];
    const float* loop1   = (const float*)d_in[4];
    const float* loop_r  = (const float*)d_in[5];
    const float* bias    = (const float*)d_in[6];
    const float* lin1_w  = (const float*)d_in[7];
    const float* lin1_b  = (const float*)d_in[8];
    const float* lin2_w  = (const float*)d_in[9];
    const float* lin2_b  = (const float*)d_in[10];
    const int*   src     = (const int*)d_in[11];
    const int*   dst     = (const int*)d_in[12];
    const int*   etype   = (const int*)d_in[13];
    const int*   gids    = (const int*)d_in[14];
    float* out = (float*)d_out;

    // resolve device-global addresses (host side, cached by runtime; no allocs)
    float *aggA, *aggB, *s0, *s1, *s2;
    cudaGetSymbolAddress((void**)&aggA, g_aggA);
    cudaGetSymbolAddress((void**)&aggB, g_aggB);
    cudaGetSymbolAddress((void**)&s0, g_s0);
    cudaGetSymbolAddress((void**)&s1, g_s1);
    cudaGetSymbolAddress((void**)&s2, g_s2);

    const int denseBlocks = (N_NODES + 7) / 8;      // warp per node, 8 warps/block
    const int edgeBlocks  = 1480;

    zero_kernel<<<400, 512>>>();
    computeW_kernel<<<(3 * IN_DIM * HID + 9 * HID * HID + 255) / 256, 256>>>(basis1, basis_r, w_comp);

    // CSR build
    hist_kernel<<<edgeBlocks, 256>>>(dst);
    scan_kernel<<<1, 1024>>>();
    scatter_kernel<<<edgeBlocks, 256>>>(src, dst, etype);

    // Layer 1
    dense0_kernel<<<denseBlocks, 256>>>(x, loop1, bias);
    pull_kernel<<<denseBlocks, 256>>>(aggA);
    // Layer 2
    denseR_kernel<<<denseBlocks, 256>>>(aggA, s0, aggB, 0 * 3 * HID * HID,
                                        loop_r + 0 * HID * HID, bias + 1 * HID);
    pull_kernel<<<denseBlocks, 256>>>(aggB);
    // Layer 3
    denseR_kernel<<<denseBlocks, 256>>>(aggB, s1, aggA, 1 * 3 * HID * HID,
                                        loop_r + 1 * HID * HID, bias + 2 * HID);
    pull_kernel<<<denseBlocks, 256>>>(aggA);
    // Layer 4
    denseR_kernel<<<denseBlocks, 256>>>(aggA, s2, aggB, 2 * 3 * HID * HID,
                                        loop_r + 2 * HID * HID, bias + 3 * HID);
    pull_kernel<<<denseBlocks, 256>>>(aggB);

    // Pool + MLP
    pool_kernel<<<(N_NODES + POOL_NODES - 1) / POOL_NODES, 128>>>(gids);
    mlp_kernel<<<N_GRAPH, 64>>>(lin1_w, lin1_b, lin2_w, lin2_b, out);
}

// round 2
// speedup vs baseline: 1.0822x; 1.0822x over previous
#include <cuda_runtime.h>
#include <cuda_fp16.h>
#include <cuda_bf16.h>
#include <math.h>

// Problem constants (fixed shapes per reference)
#define N_NODES 100000
#define IN_DIM  64
#define HID     32
#define N_EDGES 1600000
#define N_REL   3
#define N_GRAPH 256
#define SCAN_B  1024
#define NBLK    ((N_NODES + SCAN_B - 1) / SCAN_B)   // 98

// ---------------- device scratch (no allocations allowed) ----------------
__device__ __half g_rel[(size_t)N_REL * N_NODES * HID];  // [r][n][32] fp16 messages
__device__ float g_aggA[N_NODES * HID];
__device__ float g_aggB[N_NODES * HID];
__device__ float g_s0[N_NODES * HID];
__device__ float g_s1[N_NODES * HID];
__device__ float g_s2[N_NODES * HID];
__device__ int   g_deg[N_NODES];
__device__ int   g_cur[N_NODES];
__device__ int   g_rowptr[N_NODES + 1];
__device__ int   g_bsum[NBLK];
__device__ int   g_boff[NBLK];
__device__ int   g_edge_packed[N_EDGES];                  // src | (etype<<17)
__device__ float g_W1[3 * IN_DIM * HID];                  // layer-1 relation weights
__device__ float g_Wr[9 * HID * HID];                     // layers 2-4 relation weights
__device__ float g_pooled[N_GRAPH * 128];
__device__ int   g_cnt[N_GRAPH];

// ---------------- kernels ----------------

__global__ void zero_kernel() {
    int i = blockIdx.x * blockDim.x + threadIdx.x;
    int stride = gridDim.x * blockDim.x;
    for (int j = i; j < N_NODES; j += stride) g_deg[j] = 0;
    for (int j = i; j < N_GRAPH * 128; j += stride) g_pooled[j] = 0.0f;
    for (int j = i; j < N_GRAPH; j += stride) g_cnt[j] = 0;
}

// W[l][r] = sum_b w_comp[l,r,b] * basis[b]
__global__ void computeW_kernel(const float* __restrict__ basis1,
                                const float* __restrict__ basis_r,
                                const float* __restrict__ wcomp) {
    int i = blockIdx.x * blockDim.x + threadIdx.x;
    if (i < 3 * IN_DIM * HID) {
        int r = i / (IN_DIM * HID);
        int io = i % (IN_DIM * HID);
        g_W1[i] = wcomp[(0 * 3 + r) * 2 + 0] * basis1[0 * IN_DIM * HID + io]
                + wcomp[(0 * 3 + r) * 2 + 1] * basis1[1 * IN_DIM * HID + io];
    }
    int j = i - 3 * IN_DIM * HID;
    if (j >= 0 && j < 9 * HID * HID) {
        int l  = j / (3 * HID * HID);
        int rem = j % (3 * HID * HID);
        int r  = rem / (HID * HID);
        int io = rem % (HID * HID);
        g_Wr[j] = wcomp[((l + 1) * 3 + r) * 2 + 0] * basis_r[(l * 2 + 0) * HID * HID + io]
                + wcomp[((l + 1) * 3 + r) * 2 + 1] * basis_r[(l * 2 + 1) * HID * HID + io];
    }
}

__global__ void hist_kernel(const int* __restrict__ dst) {
    int i = blockIdx.x * blockDim.x + threadIdx.x;
    int stride = gridDim.x * blockDim.x;
    for (int e = i; e < N_EDGES; e += stride) atomicAdd(&g_deg[dst[e]], 1);
}

// ---- 3-phase multi-block exclusive scan of g_deg -> g_rowptr (and g_cur) ----

__global__ void blocksum_kernel() {
    __shared__ int ws[32];
    int i = blockIdx.x * SCAN_B + threadIdx.x;
    int v = (i < N_NODES) ? g_deg[i] : 0;
    int lane = threadIdx.x & 31, wid = threadIdx.x >> 5;
    #pragma unroll
    for (int o = 16; o > 0; o >>= 1) v += __shfl_down_sync(0xffffffffu, v, o);
    if (lane == 0) ws[wid] = v;
    __syncthreads();
    if (wid == 0) {
        int s = ws[lane];
        #pragma unroll
        for (int o = 16; o > 0; o >>= 1) s += __shfl_down_sync(0xffffffffu, s, o);
        if (lane == 0) g_bsum[blockIdx.x] = s;
    }
}

__global__ void scanpartials_kernel() {
    // 1 block, 128 threads scans NBLK(=98) partials
    __shared__ int ws[4];
    int t = threadIdx.x, lane = t & 31, wid = t >> 5;
    int v = (t < NBLK) ? g_bsum[t] : 0;
    int x = v;
    #pragma unroll
    for (int o = 1; o < 32; o <<= 1) {
        int tt = __shfl_up_sync(0xffffffffu, x, o);
        if (lane >= o) x += tt;
    }
    if (lane == 31) ws[wid] = x;
    __syncthreads();
    int pre = 0;
    for (int w = 0; w < wid; w++) pre += ws[w];
    int incl = pre + x;
    if (t < NBLK) g_boff[t] = incl - v;
    if (t == 127) g_rowptr[N_NODES] = incl;
}

__global__ void writerowptr_kernel() {
    __shared__ int ws[32];
    int i = blockIdx.x * SCAN_B + threadIdx.x;
    int lane = threadIdx.x & 31, wid = threadIdx.x >> 5;
    int v = (i < N_NODES) ? g_deg[i] : 0;
    int x = v;
    #pragma unroll
    for (int o = 1; o < 32; o <<= 1) {
        int t = __shfl_up_sync(0xffffffffu, x, o);
        if (lane >= o) x += t;
    }
    if (lane == 31) ws[wid] = x;
    __syncthreads();
    if (wid == 0) {
        int s = ws[lane];
        #pragma unroll
        for (int o = 1; o < 32; o <<= 1) {
            int t = __shfl_up_sync(0xffffffffu, s, o);
            if (lane >= o) s += t;
        }
        ws[lane] = s;
    }
    __syncthreads();
    int pre = (wid > 0) ? ws[wid - 1] : 0;
    int excl = g_boff[blockIdx.x] + pre + (x - v);
    if (i < N_NODES) { g_rowptr[i] = excl; g_cur[i] = excl; }
}

__global__ void scatter_kernel(const int* __restrict__ src,
                               const int* __restrict__ dst,
                               const int* __restrict__ etype) {
    int i = blockIdx.x * blockDim.x + threadIdx.x;
    int stride = gridDim.x * blockDim.x;
    for (int e = i; e < N_EDGES; e += stride) {
        int p = atomicAdd(&g_cur[dst[e]], 1);       // g_cur pre-seeded with row starts
        g_edge_packed[p] = src[e] | (etype[e] << 17);
    }
}

// Layer 1 dense: warp per node. rel[r][n] = x[n] @ W1[r]; agg = x[n]@loop1 + bias0
__global__ void dense0_kernel(const float* __restrict__ x,
                              const float* __restrict__ loop1,
                              const float* __restrict__ bias) {
    __shared__ float sW[4 * IN_DIM * HID];   // 32KB: rel0,rel1,rel2,loop
    int tid = threadIdx.x;
    for (int i = tid; i < 4 * IN_DIM * HID; i += 256)
        sW[i] = (i < 3 * IN_DIM * HID) ? g_W1[i] : loop1[i - 3 * IN_DIM * HID];
    __syncthreads();
    int lane = tid & 31, w = tid >> 5;
    int n = blockIdx.x * 8 + w;
    if (n >= N_NODES) return;
    float h0 = x[n * IN_DIM + lane];
    float h1 = x[n * IN_DIM + 32 + lane];
    float a0 = 0.f, a1 = 0.f, a2 = 0.f, aL = 0.f;
    #pragma unroll
    for (int i = 0; i < 32; i++) {
        float hv = __shfl_sync(0xffffffffu, h0, i);
        a0 += hv * sW[0 * 2048 + i * 32 + lane];
        a1 += hv * sW[1 * 2048 + i * 32 + lane];
        a2 += hv * sW[2 * 2048 + i * 32 + lane];
        aL += hv * sW[3 * 2048 + i * 32 + lane];
    }
    #pragma unroll
    for (int i = 0; i < 32; i++) {
        float hv = __shfl_sync(0xffffffffu, h1, i);
        int ii = 32 + i;
        a0 += hv * sW[0 * 2048 + ii * 32 + lane];
        a1 += hv * sW[1 * 2048 + ii * 32 + lane];
        a2 += hv * sW[2 * 2048 + ii * 32 + lane];
        aL += hv * sW[3 * 2048 + ii * 32 + lane];
    }
    g_rel[(0 * N_NODES + n) * HID + lane] = __float2half(a0);
    g_rel[((size_t)1 * N_NODES + n) * HID + lane] = __float2half(a1);
    g_rel[((size_t)2 * N_NODES + n) * HID + lane] = __float2half(a2);
    g_aggA[n * HID + lane] = aL + bias[lane];   // bias row 0
}

// Layers 2-4 dense: h = tanh(aggIn); store state; rel & self-loop init for next agg
__global__ void denseR_kernel(const float* __restrict__ aggIn,
                              float* __restrict__ stateOut,
                              float* __restrict__ aggOut,
                              int wOffset,
                              const float* __restrict__ loopW,
                              const float* __restrict__ biasRow) {
    __shared__ float sW[4 * HID * HID];   // 16KB
    int tid = threadIdx.x;
    for (int i = tid; i < 4 * HID * HID; i += 256)
        sW[i] = (i < 3 * HID * HID) ? g_Wr[wOffset + i] : loopW[i - 3 * HID * HID];
    __syncthreads();
    int lane = tid & 31, w = tid >> 5;
    int n = blockIdx.x * 8 + w;
    if (n >= N_NODES) return;
    float h = tanhf(aggIn[n * HID + lane]);
    stateOut[n * HID + lane] = h;
    float a0 = 0.f, a1 = 0.f, a2 = 0.f, aL = 0.f;
    #pragma unroll
    for (int i = 0; i < 32; i++) {
        float hv = __shfl_sync(0xffffffffu, h, i);
        a0 += hv * sW[0 * 1024 + i * 32 + lane];
        a1 += hv * sW[1 * 1024 + i * 32 + lane];
        a2 += hv * sW[2 * 1024 + i * 32 + lane];
        aL += hv * sW[3 * 1024 + i * 32 + lane];
    }
    g_rel[(0 * N_NODES + n) * HID + lane] = __float2half(a0);
    g_rel[((size_t)1 * N_NODES + n) * HID + lane] = __float2half(a1);
    g_rel[((size_t)2 * N_NODES + n) * HID + lane] = __float2half(a2);
    aggOut[n * HID + lane] = aL + biasRow[lane];
}

// Pull aggregation: warp per dst node, no atomics, fp16 gathers, 4-wide MLP
__global__ void pull_kernel(float* __restrict__ agg) {
    int gw = (blockIdx.x * blockDim.x + threadIdx.x) >> 5;
    int lane = threadIdx.x & 31;
    if (gw >= N_NODES) return;
    int k = g_rowptr[gw], end = g_rowptr[gw + 1];
    float acc = agg[gw * HID + lane];
    for (; k + 3 < end; k += 4) {
        int p0 = __ldg(&g_edge_packed[k]);
        int p1 = __ldg(&g_edge_packed[k + 1]);
        int p2 = __ldg(&g_edge_packed[k + 2]);
        int p3 = __ldg(&g_edge_packed[k + 3]);
        float v0 = __half2float(g_rel[((size_t)(p0 >> 17) * N_NODES + (p0 & 0x1FFFF)) * HID + lane]);
        float v1 = __half2float(g_rel[((size_t)(p1 >> 17) * N_NODES + (p1 & 0x1FFFF)) * HID + lane]);
        float v2 = __half2float(g_rel[((size_t)(p2 >> 17) * N_NODES + (p2 & 0x1FFFF)) * HID + lane]);
        float v3 = __half2float(g_rel[((size_t)(p3 >> 17) * N_NODES + (p3 & 0x1FFFF)) * HID + lane]);
        acc += (v0 + v1) + (v2 + v3);
    }
    for (; k < end; k++) {
        int p0 = __ldg(&g_edge_packed[k]);
        acc += __half2float(g_rel[((size_t)(p0 >> 17) * N_NODES + (p0 & 0x1FFFF)) * HID + lane]);
    }
    agg[gw * HID + lane] = acc;
}

// Mean-pool over sorted graph_ids: run-length accumulate, few atomics
#define POOL_NODES 256
__global__ void pool_kernel(const int* __restrict__ gids) {
    __shared__ int sg[POOL_NODES];
    int f = threadIdx.x;             // 128 threads: one feature each
    int base = blockIdx.x * POOL_NODES;
    for (int j = f; j < POOL_NODES; j += 128) {
        int n = base + j;
        sg[j] = (n < N_NODES) ? gids[n] : -1;
    }
    __syncthreads();
    int nn = N_NODES - base;
    if (nn > POOL_NODES) nn = POOL_NODES;
    float acc = 0.f; int curg = -1; int run = 0;
    for (int j = 0; j < nn; j++) {
        int n = base + j;
        float v;
        if (f < 32)       v = g_s0[n * HID + f];
        else if (f < 64)  v = g_s1[n * HID + (f - 32)];
        else if (f < 96)  v = g_s2[n * HID + (f - 64)];
        else              v = tanhf(g_aggB[n * HID + (f - 96)]);
        int g = sg[j];
        if (g != curg) {
            if (curg >= 0) {
                atomicAdd(&g_pooled[curg * 128 + f], acc);
                if (f == 0) atomicAdd(&g_cnt[curg], run);
            }
            curg = g; acc = 0.f; run = 0;
        }
        acc += v; run++;
    }
    if (curg >= 0) {
        atomicAdd(&g_pooled[curg * 128 + f], acc);
        if (f == 0) atomicAdd(&g_cnt[curg], run);
    }
}

// Final MLP: one block per graph, 64 threads
__global__ void mlp_kernel(const float* __restrict__ lin1_w,
                           const float* __restrict__ lin1_b,
                           const float* __restrict__ lin2_w,
                           const float* __restrict__ lin2_b,
                           float* __restrict__ out) {
    int g = blockIdx.x;
    int k = threadIdx.x;             // 0..63
    __shared__ float sp[128];
    __shared__ float partial[2];
    float cnt = (float)g_cnt[g];
    float inv = 1.0f / fmaxf(cnt, 1.0f);
    sp[k]      = g_pooled[g * 128 + k] * inv;
    sp[64 + k] = g_pooled[g * 128 + 64 + k] * inv;
    __syncthreads();
    float acc = lin1_b[k];
    #pragma unroll
    for (int j = 0; j < 128; j++) acc += sp[j] * lin1_w[j * 64 + k];
    float h = fmaxf(acc, 0.0f);
    float t = h * lin2_w[k];
    #pragma unroll
    for (int o = 16; o > 0; o >>= 1) t += __shfl_down_sync(0xffffffffu, t, o);
    if ((k & 31) == 0) partial[k >> 5] = t;
    __syncthreads();
    if (k == 0) {
        float s = partial[0] + partial[1] + lin2_b[0];
        out[g] = 1.0f / (1.0f + expf(-s));
    }
}

// ---------------- launcher ----------------
extern "C" void kernel_launch(void* const* d_in, const int* in_sizes, int n_in,
                              void* d_out, int out_size) {
    const float* x       = (const float*)d_in[0];
    const float* basis1  = (const float*)d_in[1];
    const float* basis_r = (const float*)d_in[2];
    const float* w_comp  = (const float*)d_in[3];
    const float* loop1   = (const float*)d_in[4];
    const float* loop_r  = (const float*)d_in[5];
    const float* bias    = (const float*)d_in[6];
    const float* lin1_w  = (const float*)d_in[7];
    const float* lin1_b  = (const float*)d_in[8];
    const float* lin2_w  = (const float*)d_in[9];
    const float* lin2_b  = (const float*)d_in[10];
    const int*   src     = (const int*)d_in[11];
    const int*   dst     = (const int*)d_in[12];
    const int*   etype   = (const int*)d_in[13];
    const int*   gids    = (const int*)d_in[14];
    float* out = (float*)d_out;

    float *aggA, *aggB, *s0, *s1, *s2;
    cudaGetSymbolAddress((void**)&aggA, g_aggA);
    cudaGetSymbolAddress((void**)&aggB, g_aggB);
    cudaGetSymbolAddress((void**)&s0, g_s0);
    cudaGetSymbolAddress((void**)&s1, g_s1);
    cudaGetSymbolAddress((void**)&s2, g_s2);

    const int denseBlocks = (N_NODES + 7) / 8;      // warp per node, 8 warps/block
    const int edgeBlocks  = 1480;

    zero_kernel<<<400, 512>>>();
    computeW_kernel<<<(3 * IN_DIM * HID + 9 * HID * HID + 255) / 256, 256>>>(basis1, basis_r, w_comp);

    // CSR build
    hist_kernel<<<edgeBlocks, 256>>>(dst);
    blocksum_kernel<<<NBLK, SCAN_B>>>();
    scanpartials_kernel<<<1, 128>>>();
    writerowptr_kernel<<<NBLK, SCAN_B>>>();
    scatter_kernel<<<edgeBlocks, 256>>>(src, dst, etype);

    // Layer 1
    dense0_kernel<<<denseBlocks, 256>>>(x, loop1, bias);
    pull_kernel<<<denseBlocks, 256>>>(aggA);
    // Layer 2
    denseR_kernel<<<denseBlocks, 256>>>(aggA, s0, aggB, 0 * 3 * HID * HID,
                                        loop_r + 0 * HID * HID, bias + 1 * HID);
    pull_kernel<<<denseBlocks, 256>>>(aggB);
    // Layer 3
    denseR_kernel<<<denseBlocks, 256>>>(aggB, s1, aggA, 1 * 3 * HID * HID,
                                        loop_r + 1 * HID * HID, bias + 2 * HID);
    pull_kernel<<<denseBlocks, 256>>>(aggA);
    // Layer 4
    denseR_kernel<<<denseBlocks, 256>>>(aggA, s2, aggB, 2 * 3 * HID * HID,
                                        loop_r + 2 * HID * HID, bias + 3 * HID);
    pull_kernel<<<denseBlocks, 256>>>(aggB);

    // Pool + MLP
    pool_kernel<<<(N_NODES + POOL_NODES - 1) / POOL_NODES, 128>>>(gids);
    mlp_kernel<<<N_GRAPH, 64>>>(lin1_w, lin1_b, lin2_w, lin2_b, out);
}

// round 3
// speedup vs baseline: 1.1889x; 1.0986x over previous
#include <cuda_runtime.h>
#include <cuda_fp16.h>
#include <math.h>

#define N_NODES 100000
#define IN_DIM  64
#define HID     32
#define N_EDGES 1600000
#define N_GRAPH 256
#define SCAN_B  1024
#define NBLK    ((N_NODES + SCAN_B - 1) / SCAN_B)   // 98

// ---------------- device scratch ----------------
__device__ __half g_relA[(size_t)3 * N_NODES * HID];
__device__ __half g_relB[(size_t)3 * N_NODES * HID];
__device__ float g_aggA[N_NODES * HID];
__device__ float g_aggB[N_NODES * HID];
__device__ float g_s0[N_NODES * HID];
__device__ float g_s1[N_NODES * HID];
__device__ float g_s2[N_NODES * HID];
__device__ float g_s3[N_NODES * HID];
__device__ int   g_deg[N_NODES];
__device__ int   g_cur[N_NODES];
__device__ int   g_rowptr[N_NODES + 1];
__device__ int   g_bsum[NBLK];
__device__ int   g_edge_packed[N_EDGES];        // src | (etype<<17)
__device__ float g_W1[3 * IN_DIM * HID];        // layer-1 relation weights
__device__ float g_Wf[3 * 4 * HID * HID];       // layers 2-4: [layer][rel0,rel1,rel2,loop][32][32]
__device__ float g_pooled[N_GRAPH * 128];
__device__ int   g_cnt[N_GRAPH];

// ---------------- init: zero + weight combine ----------------
__global__ void init_kernel(const float* __restrict__ basis1,
                            const float* __restrict__ basis_r,
                            const float* __restrict__ loop_r,
                            const float* __restrict__ wcomp) {
    int i = blockIdx.x * blockDim.x + threadIdx.x;
    int stride = gridDim.x * blockDim.x;
    for (int j = i; j < N_NODES; j += stride) g_deg[j] = 0;
    for (int j = i; j < N_GRAPH * 128; j += stride) g_pooled[j] = 0.0f;
    for (int j = i; j < N_GRAPH; j += stride) g_cnt[j] = 0;
    for (int j = i; j < 3 * IN_DIM * HID; j += stride) {
        int r = j / (IN_DIM * HID);
        int io = j % (IN_DIM * HID);
        g_W1[j] = wcomp[(0 * 3 + r) * 2 + 0] * basis1[0 * IN_DIM * HID + io]
                + wcomp[(0 * 3 + r) * 2 + 1] * basis1[1 * IN_DIM * HID + io];
    }
    for (int j = i; j < 3 * 4 * HID * HID; j += stride) {
        int l  = j / (4 * HID * HID);
        int m  = (j / (HID * HID)) % 4;
        int io = j % (HID * HID);
        if (m < 3)
            g_Wf[j] = wcomp[((l + 1) * 3 + m) * 2 + 0] * basis_r[(l * 2 + 0) * HID * HID + io]
                    + wcomp[((l + 1) * 3 + m) * 2 + 1] * basis_r[(l * 2 + 1) * HID * HID + io];
        else
            g_Wf[j] = loop_r[l * HID * HID + io];
    }
}

// ---------------- CSR build ----------------
__global__ void hist_kernel(const int* __restrict__ dst) {
    const int4* d4 = (const int4*)dst;
    int i = blockIdx.x * blockDim.x + threadIdx.x;
    int stride = gridDim.x * blockDim.x;
    for (int e = i; e < N_EDGES / 4; e += stride) {
        int4 d = __ldg(&d4[e]);
        atomicAdd(&g_deg[d.x], 1);
        atomicAdd(&g_deg[d.y], 1);
        atomicAdd(&g_deg[d.z], 1);
        atomicAdd(&g_deg[d.w], 1);
    }
}

__global__ void blocksum_kernel() {
    __shared__ int ws[32];
    int i = blockIdx.x * SCAN_B + threadIdx.x;
    int v = (i < N_NODES) ? g_deg[i] : 0;
    int lane = threadIdx.x & 31, wid = threadIdx.x >> 5;
    #pragma unroll
    for (int o = 16; o > 0; o >>= 1) v += __shfl_down_sync(0xffffffffu, v, o);
    if (lane == 0) ws[wid] = v;
    __syncthreads();
    if (wid == 0) {
        int s = ws[lane];
        #pragma unroll
        for (int o = 16; o > 0; o >>= 1) s += __shfl_down_sync(0xffffffffu, s, o);
        if (lane == 0) g_bsum[blockIdx.x] = s;
    }
}

// merged: each block computes its global offset from partials, scans its chunk,
// writes rowptr + seeds g_cur
__global__ void scanwrite_kernel() {
    __shared__ int ws[32];
    __shared__ int ws2[32];
    __shared__ int s_off;
    int t = threadIdx.x, lane = t & 31, wid = t >> 5;
    // offset = sum of bsum[j], j < blockIdx.x
    int v = (t < NBLK && t < blockIdx.x) ? g_bsum[t] : 0;
    #pragma unroll
    for (int o = 16; o > 0; o >>= 1) v += __shfl_down_sync(0xffffffffu, v, o);
    if (lane == 0) ws2[wid] = v;
    __syncthreads();
    if (wid == 0) {
        int s = ws2[lane];
        #pragma unroll
        for (int o = 16; o > 0; o >>= 1) s += __shfl_down_sync(0xffffffffu, s, o);
        if (lane == 0) s_off = s;
    }
    __syncthreads();
    // chunk scan
    int i = blockIdx.x * SCAN_B + t;
    int d = (i < N_NODES) ? g_deg[i] : 0;
    int x = d;
    #pragma unroll
    for (int o = 1; o < 32; o <<= 1) {
        int tt = __shfl_up_sync(0xffffffffu, x, o);
        if (lane >= o) x += tt;
    }
    if (lane == 31) ws[wid] = x;
    __syncthreads();
    if (wid == 0) {
        int s = ws[lane];
        #pragma unroll
        for (int o = 1; o < 32; o <<= 1) {
            int tt = __shfl_up_sync(0xffffffffu, s, o);
            if (lane >= o) s += tt;
        }
        ws[lane] = s;
    }
    __syncthreads();
    int pre = (wid > 0) ? ws[wid - 1] : 0;
    int excl = s_off + pre + (x - d);
    if (i < N_NODES) { g_rowptr[i] = excl; g_cur[i] = excl; }
    if (blockIdx.x == NBLK - 1 && t == SCAN_B - 1)
        g_rowptr[N_NODES] = s_off + ws[31];
}

__global__ void scatter_kernel(const int* __restrict__ src,
                               const int* __restrict__ dst,
                               const int* __restrict__ etype) {
    const int4* s4 = (const int4*)src;
    const int4* d4 = (const int4*)dst;
    const int4* t4 = (const int4*)etype;
    int i = blockIdx.x * blockDim.x + threadIdx.x;
    int stride = gridDim.x * blockDim.x;
    for (int e = i; e < N_EDGES / 4; e += stride) {
        int4 s = __ldg(&s4[e]);
        int4 d = __ldg(&d4[e]);
        int4 r = __ldg(&t4[e]);
        int p;
        p = atomicAdd(&g_cur[d.x], 1); g_edge_packed[p] = s.x | (r.x << 17);
        p = atomicAdd(&g_cur[d.y], 1); g_edge_packed[p] = s.y | (r.y << 17);
        p = atomicAdd(&g_cur[d.z], 1); g_edge_packed[p] = s.z | (r.z << 17);
        p = atomicAdd(&g_cur[d.w], 1); g_edge_packed[p] = s.w | (r.w << 17);
    }
}

// ---------------- layer 1 dense ----------------
__global__ void dense0_kernel(const float* __restrict__ x,
                              const float* __restrict__ loop1,
                              const float* __restrict__ bias) {
    __shared__ float sW[4 * IN_DIM * HID];   // 32KB: rel0,rel1,rel2,loop
    int tid = threadIdx.x;
    for (int i = tid; i < 4 * IN_DIM * HID; i += 256)
        sW[i] = (i < 3 * IN_DIM * HID) ? g_W1[i] : loop1[i - 3 * IN_DIM * HID];
    __syncthreads();
    int lane = tid & 31, w = tid >> 5;
    int n = blockIdx.x * 8 + w;
    if (n >= N_NODES) return;
    float h0 = x[n * IN_DIM + lane];
    float h1 = x[n * IN_DIM + 32 + lane];
    float a0 = 0.f, a1 = 0.f, a2 = 0.f, aL = 0.f;
    #pragma unroll
    for (int i = 0; i < 32; i++) {
        float hv = __shfl_sync(0xffffffffu, h0, i);
        a0 += hv * sW[0 * 2048 + i * 32 + lane];
        a1 += hv * sW[1 * 2048 + i * 32 + lane];
        a2 += hv * sW[2 * 2048 + i * 32 + lane];
        aL += hv * sW[3 * 2048 + i * 32 + lane];
    }
    #pragma unroll
    for (int i = 0; i < 32; i++) {
        float hv = __shfl_sync(0xffffffffu, h1, i);
        int ii = 32 + i;
        a0 += hv * sW[0 * 2048 + ii * 32 + lane];
        a1 += hv * sW[1 * 2048 + ii * 32 + lane];
        a2 += hv * sW[2 * 2048 + ii * 32 + lane];
        aL += hv * sW[3 * 2048 + ii * 32 + lane];
    }
    g_relA[(0 * N_NODES + n) * HID + lane] = __float2half(a0);
    g_relA[((size_t)1 * N_NODES + n) * HID + lane] = __float2half(a1);
    g_relA[((size_t)2 * N_NODES + n) * HID + lane] = __float2half(a2);
    g_aggA[n * HID + lane] = aL + bias[lane];
}

// ---------------- fused pull + tanh + next-layer dense ----------------
// 8 lanes per edge (uint2 = 4 halves), 4 edges per warp-iteration.
__global__ void fused_kernel(const __half* __restrict__ relIn,
                             const float* __restrict__ aggIn,
                             __half* __restrict__ relOut,
                             float* __restrict__ aggOut,
                             float* __restrict__ stateOut,
                             const float* __restrict__ Wf,      // [4][32][32]
                             const float* __restrict__ biasRow) // next-layer bias
{
    __shared__ float sW[4 * HID * HID];
    int tid = threadIdx.x;
    for (int i = tid; i < 4 * HID * HID; i += 256) sW[i] = Wf[i];
    __syncthreads();
    int warp = tid >> 5, lane = tid & 31;
    int n = blockIdx.x * 8 + warp;
    if (n >= N_NODES) return;
    int m = lane >> 3;          // edge-sublane / matvec id
    int c = lane & 7;           // feature chunk (4 floats)
    int k = g_rowptr[n], end = g_rowptr[n + 1];
    float a0 = 0.f, a1 = 0.f, a2 = 0.f, a3 = 0.f;
    for (; k < end; k += 4) {
        int p = 0;
        if (lane < 4 && (k + lane) < end) p = g_edge_packed[k + lane];
        p = __shfl_sync(0xffffffffu, p, m);
        if (k + m < end) {
            int s = p & 0x1FFFF, r = p >> 17;
            const uint2* row = (const uint2*)(relIn + ((size_t)r * N_NODES + s) * HID);
            uint2 v = __ldg(&row[c]);
            __half2 hlo = *(__half2*)&v.x;
            __half2 hhi = *(__half2*)&v.y;
            float2 f0 = __half22float2(hlo);
            float2 f1 = __half22float2(hhi);
            a0 += f0.x; a1 += f0.y; a2 += f1.x; a3 += f1.y;
        }
    }
    // combine across the 4 edge-sublane groups
    #pragma unroll
    for (int o = 8; o <= 16; o <<= 1) {
        a0 += __shfl_xor_sync(0xffffffffu, a0, o);
        a1 += __shfl_xor_sync(0xffffffffu, a1, o);
        a2 += __shfl_xor_sync(0xffffffffu, a2, o);
        a3 += __shfl_xor_sync(0xffffffffu, a3, o);
    }
    float4 sl = ((const float4*)aggIn)[n * 8 + c];
    float h0 = tanhf(a0 + sl.x);
    float h1 = tanhf(a1 + sl.y);
    float h2 = tanhf(a2 + sl.z);
    float h3 = tanhf(a3 + sl.w);
    if (m == 0)
        ((float4*)stateOut)[n * 8 + c] = make_float4(h0, h1, h2, h3);
    // dense: matvec m, outputs c*4..c*4+3
    float hreg[4] = {h0, h1, h2, h3};
    int grp = lane & 24;
    float o0 = 0.f, o1 = 0.f, o2 = 0.f, o3 = 0.f;
    #pragma unroll
    for (int i = 0; i < 32; i++) {
        float hv = __shfl_sync(0xffffffffu, hreg[i & 3], grp | (i >> 2));
        float4 w = *(const float4*)&sW[(m * 32 + i) * 32 + c * 4];
        o0 += hv * w.x; o1 += hv * w.y; o2 += hv * w.z; o3 += hv * w.w;
    }
    if (m < 3) {
        __half2 ha = __floats2half2_rn(o0, o1);
        __half2 hb = __floats2half2_rn(o2, o3);
        uint2 pk;
        pk.x = *reinterpret_cast<unsigned int*>(&ha);
        pk.y = *reinterpret_cast<unsigned int*>(&hb);
        ((uint2*)relOut)[((size_t)m * N_NODES + n) * 8 + c] = pk;
    } else {
        float4 b4 = ((const float4*)biasRow)[c];
        ((float4*)aggOut)[n * 8 + c] = make_float4(o0 + b4.x, o1 + b4.y, o2 + b4.z, o3 + b4.w);
    }
}

// final layer: pull + tanh only
__global__ void final_kernel(const __half* __restrict__ relIn,
                             const float* __restrict__ aggIn,
                             float* __restrict__ stateOut)
{
    int warp = threadIdx.x >> 5, lane = threadIdx.x & 31;
    int n = blockIdx.x * 8 + warp;
    if (n >= N_NODES) return;
    int m = lane >> 3, c = lane & 7;
    int k = g_rowptr[n], end = g_rowptr[n + 1];
    float a0 = 0.f, a1 = 0.f, a2 = 0.f, a3 = 0.f;
    for (; k < end; k += 4) {
        int p = 0;
        if (lane < 4 && (k + lane) < end) p = g_edge_packed[k + lane];
        p = __shfl_sync(0xffffffffu, p, m);
        if (k + m < end) {
            int s = p & 0x1FFFF, r = p >> 17;
            const uint2* row = (const uint2*)(relIn + ((size_t)r * N_NODES + s) * HID);
            uint2 v = __ldg(&row[c]);
            __half2 hlo = *(__half2*)&v.x;
            __half2 hhi = *(__half2*)&v.y;
            float2 f0 = __half22float2(hlo);
            float2 f1 = __half22float2(hhi);
            a0 += f0.x; a1 += f0.y; a2 += f1.x; a3 += f1.y;
        }
    }
    #pragma unroll
    for (int o = 8; o <= 16; o <<= 1) {
        a0 += __shfl_xor_sync(0xffffffffu, a0, o);
        a1 += __shfl_xor_sync(0xffffffffu, a1, o);
        a2 += __shfl_xor_sync(0xffffffffu, a2, o);
        a3 += __shfl_xor_sync(0xffffffffu, a3, o);
    }
    if (m == 0) {
        float4 sl = ((const float4*)aggIn)[n * 8 + c];
        ((float4*)stateOut)[n * 8 + c] =
            make_float4(tanhf(a0 + sl.x), tanhf(a1 + sl.y), tanhf(a2 + sl.z), tanhf(a3 + sl.w));
    }
}

// ---------------- pooling over sorted graph_ids ----------------
#define POOL_NODES 256
__global__ void pool_kernel(const int* __restrict__ gids) {
    __shared__ int sg[POOL_NODES];
    int f = threadIdx.x;             // 128 threads: one feature each
    int base = blockIdx.x * POOL_NODES;
    for (int j = f; j < POOL_NODES; j += 128) {
        int n = base + j;
        sg[j] = (n < N_NODES) ? gids[n] : -1;
    }
    __syncthreads();
    int nn = N_NODES - base;
    if (nn > POOL_NODES) nn = POOL_NODES;
    float acc = 0.f; int curg = -1; int run = 0;
    for (int j = 0; j < nn; j++) {
        int n = base + j;
        float v;
        if (f < 32)       v = g_s0[n * HID + f];
        else if (f < 64)  v = g_s1[n * HID + (f - 32)];
        else if (f < 96)  v = g_s2[n * HID + (f - 64)];
        else              v = g_s3[n * HID + (f - 96)];
        int g = sg[j];
        if (g != curg) {
            if (curg >= 0) {
                atomicAdd(&g_pooled[curg * 128 + f], acc);
                if (f == 0) atomicAdd(&g_cnt[curg], run);
            }
            curg = g; acc = 0.f; run = 0;
        }
        acc += v; run++;
    }
    if (curg >= 0) {
        atomicAdd(&g_pooled[curg * 128 + f], acc);
        if (f == 0) atomicAdd(&g_cnt[curg], run);
    }
}

// ---------------- final MLP ----------------
__global__ void mlp_kernel(const float* __restrict__ lin1_w,
                           const float* __restrict__ lin1_b,
                           const float* __restrict__ lin2_w,
                           const float* __restrict__ lin2_b,
                           float* __restrict__ out) {
    int g = blockIdx.x;
    int k = threadIdx.x;             // 0..63
    __shared__ float sp[128];
    __shared__ float partial[2];
    float cnt = (float)g_cnt[g];
    float inv = 1.0f / fmaxf(cnt, 1.0f);
    sp[k]      = g_pooled[g * 128 + k] * inv;
    sp[64 + k] = g_pooled[g * 128 + 64 + k] * inv;
    __syncthreads();
    float acc = lin1_b[k];
    #pragma unroll
    for (int j = 0; j < 128; j++) acc += sp[j] * lin1_w[j * 64 + k];
    float h = fmaxf(acc, 0.0f);
    float t = h * lin2_w[k];
    #pragma unroll
    for (int o = 16; o > 0; o >>= 1) t += __shfl_down_sync(0xffffffffu, t, o);
    if ((k & 31) == 0) partial[k >> 5] = t;
    __syncthreads();
    if (k == 0) {
        float s = partial[0] + partial[1] + lin2_b[0];
        out[g] = 1.0f / (1.0f + expf(-s));
    }
}

// ---------------- launcher ----------------
extern "C" void kernel_launch(void* const* d_in, const int* in_sizes, int n_in,
                              void* d_out, int out_size) {
    const float* x       = (const float*)d_in[0];
    const float* basis1  = (const float*)d_in[1];
    const float* basis_r = (const float*)d_in[2];
    const float* w_comp  = (const float*)d_in[3];
    const float* loop1   = (const float*)d_in[4];
    const float* loop_r  = (const float*)d_in[5];
    const float* bias    = (const float*)d_in[6];
    const float* lin1_w  = (const float*)d_in[7];
    const float* lin1_b  = (const float*)d_in[8];
    const float* lin2_w  = (const float*)d_in[9];
    const float* lin2_b  = (const float*)d_in[10];
    const int*   src     = (const int*)d_in[11];
    const int*   dst     = (const int*)d_in[12];
    const int*   etype   = (const int*)d_in[13];
    const int*   gids    = (const int*)d_in[14];
    float* out = (float*)d_out;

    __half *relA, *relB;
    float *aggA, *aggB, *s0, *s1, *s2, *s3, *Wf;
    cudaGetSymbolAddress((void**)&relA, g_relA);
    cudaGetSymbolAddress((void**)&relB, g_relB);
    cudaGetSymbolAddress((void**)&aggA, g_aggA);
    cudaGetSymbolAddress((void**)&aggB, g_aggB);
    cudaGetSymbolAddress((void**)&s0, g_s0);
    cudaGetSymbolAddress((void**)&s1, g_s1);
    cudaGetSymbolAddress((void**)&s2, g_s2);
    cudaGetSymbolAddress((void**)&s3, g_s3);
    cudaGetSymbolAddress((void**)&Wf, g_Wf);

    const int denseBlocks = (N_NODES + 7) / 8;     // warp per node
    const int edgeBlocks  = 391;                   // E/4/1024 ≈ 391 blocks of 1024 thr... use 256
    (void)edgeBlocks;

    init_kernel<<<400, 512>>>(basis1, basis_r, loop_r, w_comp);
    hist_kernel<<<800, 256>>>(dst);
    blocksum_kernel<<<NBLK, SCAN_B>>>();
    scanwrite_kernel<<<NBLK, SCAN_B>>>();
    scatter_kernel<<<800, 256>>>(src, dst, etype);

    dense0_kernel<<<denseBlocks, 256>>>(x, loop1, bias);
    // layer 2
    fused_kernel<<<denseBlocks, 256>>>(relA, aggA, relB, aggB, s0,
                                       Wf + 0 * 4 * HID * HID, bias + 1 * HID);
    // layer 3
    fused_kernel<<<denseBlocks, 256>>>(relB, aggB, relA, aggA, s1,
                                       Wf + 1 * 4 * HID * HID, bias + 2 * HID);
    // layer 4
    fused_kernel<<<denseBlocks, 256>>>(relA, aggA, relB, aggB, s2,
                                       Wf + 2 * 4 * HID * HID, bias + 3 * HID);
    // final pull + tanh
    final_kernel<<<denseBlocks, 256>>>(relB, aggB, s3);

    pool_kernel<<<(N_NODES + POOL_NODES - 1) / POOL_NODES, 128>>>(gids);
    mlp_kernel<<<N_GRAPH, 64>>>(lin1_w, lin1_b, lin2_w, lin2_b, out);
}

// round 4
// speedup vs baseline: 1.4047x; 1.1814x over previous
#include <cuda_runtime.h>
#include <cuda_fp16.h>
#include <math.h>

#define N_NODES 100000
#define IN_DIM  64
#define HID     32
#define N_EDGES 1600000
#define N_GRAPH 256
#define SCAN_B  1024
#define NBLK    ((N_NODES + SCAN_B - 1) / SCAN_B)   // 98

// ---------------- device scratch ----------------
__device__ __half g_relA[(size_t)3 * N_NODES * HID];
__device__ __half g_relB[(size_t)3 * N_NODES * HID];
__device__ float g_aggA[N_NODES * HID];
__device__ float g_aggB[N_NODES * HID];
__device__ float g_s0[N_NODES * HID];
__device__ float g_s1[N_NODES * HID];
__device__ float g_s2[N_NODES * HID];
__device__ float g_s3[N_NODES * HID];
__device__ int   g_deg[N_NODES];
__device__ int   g_cur[N_NODES];
__device__ int   g_rowptr[N_NODES + 1];
__device__ int   g_bsum[NBLK];
__device__ int   g_edge_packed[N_EDGES];        // src | (etype<<17)
__device__ float g_W1[3 * IN_DIM * HID];        // layer-1 relation weights [r][in][out]
__device__ float g_Wf[3 * 4 * HID * HID];       // layers 2-4: [layer][rel0..rel2,loop][32][32]
__device__ float g_pooled[N_GRAPH * 128];
__device__ int   g_cnt[N_GRAPH];

__device__ __forceinline__ float fast_tanh(float x) {
    float e = __expf(2.0f * x);
    return 1.0f - __fdividef(2.0f, e + 1.0f);
}

// ---------------- init: zero + weight combine ----------------
__global__ void init_kernel(const float* __restrict__ basis1,
                            const float* __restrict__ basis_r,
                            const float* __restrict__ loop_r,
                            const float* __restrict__ wcomp) {
    int i = blockIdx.x * blockDim.x + threadIdx.x;
    int stride = gridDim.x * blockDim.x;
    for (int j = i; j < N_NODES; j += stride) g_deg[j] = 0;
    for (int j = i; j < N_GRAPH * 128; j += stride) g_pooled[j] = 0.0f;
    for (int j = i; j < N_GRAPH; j += stride) g_cnt[j] = 0;
    for (int j = i; j < 3 * IN_DIM * HID; j += stride) {
        int r = j / (IN_DIM * HID);
        int io = j % (IN_DIM * HID);
        g_W1[j] = wcomp[(0 * 3 + r) * 2 + 0] * basis1[0 * IN_DIM * HID + io]
                + wcomp[(0 * 3 + r) * 2 + 1] * basis1[1 * IN_DIM * HID + io];
    }
    for (int j = i; j < 3 * 4 * HID * HID; j += stride) {
        int l  = j / (4 * HID * HID);
        int m  = (j / (HID * HID)) % 4;
        int io = j % (HID * HID);
        if (m < 3)
            g_Wf[j] = wcomp[((l + 1) * 3 + m) * 2 + 0] * basis_r[(l * 2 + 0) * HID * HID + io]
                    + wcomp[((l + 1) * 3 + m) * 2 + 1] * basis_r[(l * 2 + 1) * HID * HID + io];
        else
            g_Wf[j] = loop_r[l * HID * HID + io];
    }
}

// ---------------- CSR build ----------------
__global__ void hist_kernel(const int* __restrict__ dst) {
    const int4* d4 = (const int4*)dst;
    int i = blockIdx.x * blockDim.x + threadIdx.x;
    int stride = gridDim.x * blockDim.x;
    for (int e = i; e < N_EDGES / 4; e += stride) {
        int4 d = __ldg(&d4[e]);
        atomicAdd(&g_deg[d.x], 1);
        atomicAdd(&g_deg[d.y], 1);
        atomicAdd(&g_deg[d.z], 1);
        atomicAdd(&g_deg[d.w], 1);
    }
}

__global__ void blocksum_kernel() {
    __shared__ int ws[32];
    int i = blockIdx.x * SCAN_B + threadIdx.x;
    int v = (i < N_NODES) ? g_deg[i] : 0;
    int lane = threadIdx.x & 31, wid = threadIdx.x >> 5;
    #pragma unroll
    for (int o = 16; o > 0; o >>= 1) v += __shfl_down_sync(0xffffffffu, v, o);
    if (lane == 0) ws[wid] = v;
    __syncthreads();
    if (wid == 0) {
        int s = ws[lane];
        #pragma unroll
        for (int o = 16; o > 0; o >>= 1) s += __shfl_down_sync(0xffffffffu, s, o);
        if (lane == 0) g_bsum[blockIdx.x] = s;
    }
}

__global__ void scanwrite_kernel() {
    __shared__ int ws[32];
    __shared__ int ws2[32];
    __shared__ int s_off;
    int t = threadIdx.x, lane = t & 31, wid = t >> 5;
    int v = (t < NBLK && t < blockIdx.x) ? g_bsum[t] : 0;
    #pragma unroll
    for (int o = 16; o > 0; o >>= 1) v += __shfl_down_sync(0xffffffffu, v, o);
    if (lane == 0) ws2[wid] = v;
    __syncthreads();
    if (wid == 0) {
        int s = ws2[lane];
        #pragma unroll
        for (int o = 16; o > 0; o >>= 1) s += __shfl_down_sync(0xffffffffu, s, o);
        if (lane == 0) s_off = s;
    }
    __syncthreads();
    int i = blockIdx.x * SCAN_B + t;
    int d = (i < N_NODES) ? g_deg[i] : 0;
    int x = d;
    #pragma unroll
    for (int o = 1; o < 32; o <<= 1) {
        int tt = __shfl_up_sync(0xffffffffu, x, o);
        if (lane >= o) x += tt;
    }
    if (lane == 31) ws[wid] = x;
    __syncthreads();
    if (wid == 0) {
        int s = ws[lane];
        #pragma unroll
        for (int o = 1; o < 32; o <<= 1) {
            int tt = __shfl_up_sync(0xffffffffu, s, o);
            if (lane >= o) s += tt;
        }
        ws[lane] = s;
    }
    __syncthreads();
    int pre = (wid > 0) ? ws[wid - 1] : 0;
    int excl = s_off + pre + (x - d);
    if (i < N_NODES) { g_rowptr[i] = excl; g_cur[i] = excl; }
    if (blockIdx.x == NBLK - 1 && t == SCAN_B - 1)
        g_rowptr[N_NODES] = s_off + ws[31];
}

__global__ void scatter_kernel(const int* __restrict__ src,
                               const int* __restrict__ dst,
                               const int* __restrict__ etype) {
    const int4* s4 = (const int4*)src;
    const int4* d4 = (const int4*)dst;
    const int4* t4 = (const int4*)etype;
    int i = blockIdx.x * blockDim.x + threadIdx.x;
    int stride = gridDim.x * blockDim.x;
    for (int e = i; e < N_EDGES / 4; e += stride) {
        int4 s = __ldg(&s4[e]);
        int4 d = __ldg(&d4[e]);
        int4 r = __ldg(&t4[e]);
        int p;
        p = atomicAdd(&g_cur[d.x], 1); g_edge_packed[p] = s.x | (r.x << 17);
        p = atomicAdd(&g_cur[d.y], 1); g_edge_packed[p] = s.y | (r.y << 17);
        p = atomicAdd(&g_cur[d.z], 1); g_edge_packed[p] = s.z | (r.z << 17);
        p = atomicAdd(&g_cur[d.w], 1); g_edge_packed[p] = s.w | (r.w << 17);
    }
}

// ---------------- layer 1 dense: tiled register-blocked GEMM ----------------
// Block: 256 threads, 64 nodes. Thread = 8 nodes x 4 output features.
#define D0_NODES 64
__global__ __launch_bounds__(256) void dense0_kernel(const float* __restrict__ x,
                              const float* __restrict__ loop1,
                              const float* __restrict__ bias) {
    __shared__ float sW[IN_DIM * 128];     // [i][f] combined: rel0|rel1|rel2|loop  (32KB)
    __shared__ float sx[D0_NODES * IN_DIM]; // 16KB
    int t = threadIdx.x;
    int base = blockIdx.x * D0_NODES;
    // load W: sW[i*128 + f]
    for (int j = t; j < IN_DIM * 128; j += 256) {
        int i = j >> 7, f = j & 127;
        int m = f >> 5, c = f & 31;
        sW[j] = (m < 3) ? g_W1[m * IN_DIM * HID + i * HID + c]
                        : loop1[i * HID + c];
    }
    // load x tile: 64 nodes x 16 float4
    {
        const float4* x4 = (const float4*)x;
        float4* sx4 = (float4*)sx;
        for (int q = 0; q < 4; q++) {
            int idx = t + 256 * q;              // 0..1023
            int node = idx >> 4, f4 = idx & 15;
            int gn = base + node;
            sx4[idx] = (gn < N_NODES) ? __ldg(&x4[gn * 16 + f4])
                                      : make_float4(0.f, 0.f, 0.f, 0.f);
        }
    }
    __syncthreads();
    int ng = t >> 5;                  // node group 0..7 (8 nodes each)
    int f = (t & 31) * 4;             // output features f..f+3
    float acc[8][4];
    #pragma unroll
    for (int j = 0; j < 8; j++) { acc[j][0] = acc[j][1] = acc[j][2] = acc[j][3] = 0.f; }
    #pragma unroll 4
    for (int i = 0; i < IN_DIM; i++) {
        float4 w = *(const float4*)&sW[i * 128 + f];
        #pragma unroll
        for (int j = 0; j < 8; j++) {
            float xv = sx[(ng * 8 + j) * IN_DIM + i];   // warp-broadcast
            acc[j][0] += xv * w.x;
            acc[j][1] += xv * w.y;
            acc[j][2] += xv * w.z;
            acc[j][3] += xv * w.w;
        }
    }
    int m = f >> 5, c = f & 31;
    #pragma unroll
    for (int j = 0; j < 8; j++) {
        int n = base + ng * 8 + j;
        if (n >= N_NODES) break;
        if (m < 3) {
            __half2 ha = __floats2half2_rn(acc[j][0], acc[j][1]);
            __half2 hb = __floats2half2_rn(acc[j][2], acc[j][3]);
            uint2 pk;
            pk.x = *reinterpret_cast<unsigned int*>(&ha);
            pk.y = *reinterpret_cast<unsigned int*>(&hb);
            *(uint2*)&g_relA[((size_t)m * N_NODES + n) * HID + c] = pk;
        } else {
            float4 b4 = *(const float4*)&bias[c];
            *(float4*)&g_aggA[n * HID + c] =
                make_float4(acc[j][0] + b4.x, acc[j][1] + b4.y,
                            acc[j][2] + b4.z, acc[j][3] + b4.w);
        }
    }
}

// ---------------- edge gather helper: prefetched indices ----------------
// Accumulates sum of rel rows for node n into a0..a3 (per-lane feature chunk c, group m).
__device__ __forceinline__ void gather_edges(const __half* __restrict__ relIn,
                                             int n, int lane, int m, int c,
                                             float& a0, float& a1, float& a2, float& a3) {
    int k0 = g_rowptr[n];
    int deg = g_rowptr[n + 1] - k0;
    for (int base = 0; base < deg; base += 32) {
        int rem = deg - base;
        int p = 0;
        if (lane < rem) p = g_edge_packed[k0 + base + lane];
        if (rem >= 32) {
            #pragma unroll
            for (int j = 0; j < 32; j += 4) {
                int pj = __shfl_sync(0xffffffffu, p, j + m);
                int s = pj & 0x1FFFF, r = pj >> 17;
                uint2 v = __ldg((const uint2*)(relIn + ((size_t)r * N_NODES + s) * HID) + c);
                __half2 hlo = *(__half2*)&v.x;
                __half2 hhi = *(__half2*)&v.y;
                float2 f0 = __half22float2(hlo);
                float2 f1 = __half22float2(hhi);
                a0 += f0.x; a1 += f0.y; a2 += f1.x; a3 += f1.y;
            }
        } else {
            for (int j = 0; j < rem; j += 4) {
                int pj = __shfl_sync(0xffffffffu, p, j + m);
                if (j + m < rem) {
                    int s = pj & 0x1FFFF, r = pj >> 17;
                    uint2 v = __ldg((const uint2*)(relIn + ((size_t)r * N_NODES + s) * HID) + c);
                    __half2 hlo = *(__half2*)&v.x;
                    __half2 hhi = *(__half2*)&v.y;
                    float2 f0 = __half22float2(hlo);
                    float2 f1 = __half22float2(hhi);
                    a0 += f0.x; a1 += f0.y; a2 += f1.x; a3 += f1.y;
                }
            }
        }
    }
}

// ---------------- fused pull + tanh + next-layer dense ----------------
__global__ __launch_bounds__(256) void fused_kernel(const __half* __restrict__ relIn,
                             const float* __restrict__ aggIn,
                             __half* __restrict__ relOut,
                             float* __restrict__ aggOut,
                             float* __restrict__ stateOut,
                             const float* __restrict__ Wf,      // [4][32][32]
                             const float* __restrict__ biasRow)
{
    __shared__ float sW[4 * HID * HID];
    int tid = threadIdx.x;
    for (int i = tid; i < 4 * HID * HID; i += 256) sW[i] = Wf[i];
    __syncthreads();
    int warp = tid >> 5, lane = tid & 31;
    int n = blockIdx.x * 8 + warp;
    if (n >= N_NODES) return;
    int m = lane >> 3;          // edge-sublane / matvec id
    int c = lane & 7;           // feature chunk (4 values)
    float a0 = 0.f, a1 = 0.f, a2 = 0.f, a3 = 0.f;
    gather_edges(relIn, n, lane, m, c, a0, a1, a2, a3);
    #pragma unroll
    for (int o = 8; o <= 16; o <<= 1) {
        a0 += __shfl_xor_sync(0xffffffffu, a0, o);
        a1 += __shfl_xor_sync(0xffffffffu, a1, o);
        a2 += __shfl_xor_sync(0xffffffffu, a2, o);
        a3 += __shfl_xor_sync(0xffffffffu, a3, o);
    }
    float4 sl = ((const float4*)aggIn)[n * 8 + c];
    float h0 = fast_tanh(a0 + sl.x);
    float h1 = fast_tanh(a1 + sl.y);
    float h2 = fast_tanh(a2 + sl.z);
    float h3 = fast_tanh(a3 + sl.w);
    if (m == 0)
        ((float4*)stateOut)[n * 8 + c] = make_float4(h0, h1, h2, h3);
    float hreg[4] = {h0, h1, h2, h3};
    int grp = lane & 24;
    float o0 = 0.f, o1 = 0.f, o2 = 0.f, o3 = 0.f;
    #pragma unroll
    for (int i = 0; i < 32; i++) {
        float hv = __shfl_sync(0xffffffffu, hreg[i & 3], grp | (i >> 2));
        float4 w = *(const float4*)&sW[(m * 32 + i) * 32 + c * 4];
        o0 += hv * w.x; o1 += hv * w.y; o2 += hv * w.z; o3 += hv * w.w;
    }
    if (m < 3) {
        __half2 ha = __floats2half2_rn(o0, o1);
        __half2 hb = __floats2half2_rn(o2, o3);
        uint2 pk;
        pk.x = *reinterpret_cast<unsigned int*>(&ha);
        pk.y = *reinterpret_cast<unsigned int*>(&hb);
        ((uint2*)relOut)[((size_t)m * N_NODES + n) * 8 + c] = pk;
    } else {
        float4 b4 = ((const float4*)biasRow)[c];
        ((float4*)aggOut)[n * 8 + c] = make_float4(o0 + b4.x, o1 + b4.y, o2 + b4.z, o3 + b4.w);
    }
}

// final layer: pull + tanh only
__global__ __launch_bounds__(256) void final_kernel(const __half* __restrict__ relIn,
                             const float* __restrict__ aggIn,
                             float* __restrict__ stateOut)
{
    int warp = threadIdx.x >> 5, lane = threadIdx.x & 31;
    int n = blockIdx.x * 8 + warp;
    if (n >= N_NODES) return;
    int m = lane >> 3, c = lane & 7;
    float a0 = 0.f, a1 = 0.f, a2 = 0.f, a3 = 0.f;
    gather_edges(relIn, n, lane, m, c, a0, a1, a2, a3);
    #pragma unroll
    for (int o = 8; o <= 16; o <<= 1) {
        a0 += __shfl_xor_sync(0xffffffffu, a0, o);
        a1 += __shfl_xor_sync(0xffffffffu, a1, o);
        a2 += __shfl_xor_sync(0xffffffffu, a2, o);
        a3 += __shfl_xor_sync(0xffffffffu, a3, o);
    }
    if (m == 0) {
        float4 sl = ((const float4*)aggIn)[n * 8 + c];
        ((float4*)stateOut)[n * 8 + c] =
            make_float4(fast_tanh(a0 + sl.x), fast_tanh(a1 + sl.y),
                        fast_tanh(a2 + sl.z), fast_tanh(a3 + sl.w));
    }
}

// ---------------- pooling over sorted graph_ids ----------------
#define POOL_NODES 256
__global__ void pool_kernel(const int* __restrict__ gids) {
    __shared__ int sg[POOL_NODES];
    int f = threadIdx.x;
    int base = blockIdx.x * POOL_NODES;
    for (int j = f; j < POOL_NODES; j += 128) {
        int n = base + j;
        sg[j] = (n < N_NODES) ? gids[n] : -1;
    }
    __syncthreads();
    int nn = N_NODES - base;
    if (nn > POOL_NODES) nn = POOL_NODES;
    float acc = 0.f; int curg = -1; int run = 0;
    for (int j = 0; j < nn; j++) {
        int n = base + j;
        float v;
        if (f < 32)       v = g_s0[n * HID + f];
        else if (f < 64)  v = g_s1[n * HID + (f - 32)];
        else if (f < 96)  v = g_s2[n * HID + (f - 64)];
        else              v = g_s3[n * HID + (f - 96)];
        int g = sg[j];
        if (g != curg) {
            if (curg >= 0) {
                atomicAdd(&g_pooled[curg * 128 + f], acc);
                if (f == 0) atomicAdd(&g_cnt[curg], run);
            }
            curg = g; acc = 0.f; run = 0;
        }
        acc += v; run++;
    }
    if (curg >= 0) {
        atomicAdd(&g_pooled[curg * 128 + f], acc);
        if (f == 0) atomicAdd(&g_cnt[curg], run);
    }
}

// ---------------- final MLP ----------------
__global__ void mlp_kernel(const float* __restrict__ lin1_w,
                           const float* __restrict__ lin1_b,
                           const float* __restrict__ lin2_w,
                           const float* __restrict__ lin2_b,
                           float* __restrict__ out) {
    int g = blockIdx.x;
    int k = threadIdx.x;
    __shared__ float sp[128];
    __shared__ float partial[2];
    float cnt = (float)g_cnt[g];
    float inv = 1.0f / fmaxf(cnt, 1.0f);
    sp[k]      = g_pooled[g * 128 + k] * inv;
    sp[64 + k] = g_pooled[g * 128 + 64 + k] * inv;
    __syncthreads();
    float acc = lin1_b[k];
    #pragma unroll
    for (int j = 0; j < 128; j++) acc += sp[j] * lin1_w[j * 64 + k];
    float h = fmaxf(acc, 0.0f);
    float t = h * lin2_w[k];
    #pragma unroll
    for (int o = 16; o > 0; o >>= 1) t += __shfl_down_sync(0xffffffffu, t, o);
    if ((k & 31) == 0) partial[k >> 5] = t;
    __syncthreads();
    if (k == 0) {
        float s = partial[0] + partial[1] + lin2_b[0];
        out[g] = 1.0f / (1.0f + expf(-s));
    }
}

// ---------------- launcher ----------------
extern "C" void kernel_launch(void* const* d_in, const int* in_sizes, int n_in,
                              void* d_out, int out_size) {
    const float* x       = (const float*)d_in[0];
    const float* basis1  = (const float*)d_in[1];
    const float* basis_r = (const float*)d_in[2];
    const float* w_comp  = (const float*)d_in[3];
    const float* loop1   = (const float*)d_in[4];
    const float* loop_r  = (const float*)d_in[5];
    const float* bias    = (const float*)d_in[6];
    const float* lin1_w  = (const float*)d_in[7];
    const float* lin1_b  = (const float*)d_in[8];
    const float* lin2_w  = (const float*)d_in[9];
    const float* lin2_b  = (const float*)d_in[10];
    const int*   src     = (const int*)d_in[11];
    const int*   dst     = (const int*)d_in[12];
    const int*   etype   = (const int*)d_in[13];
    const int*   gids    = (const int*)d_in[14];
    float* out = (float*)d_out;

    __half *relA, *relB;
    float *aggA, *aggB, *s0, *s1, *s2, *s3, *Wf;
    cudaGetSymbolAddress((void**)&relA, g_relA);
    cudaGetSymbolAddress((void**)&relB, g_relB);
    cudaGetSymbolAddress((void**)&aggA, g_aggA);
    cudaGetSymbolAddress((void**)&aggB, g_aggB);
    cudaGetSymbolAddress((void**)&s0, g_s0);
    cudaGetSymbolAddress((void**)&s1, g_s1);
    cudaGetSymbolAddress((void**)&s2, g_s2);
    cudaGetSymbolAddress((void**)&s3, g_s3);
    cudaGetSymbolAddress((void**)&Wf, g_Wf);

    const int warpBlocks = (N_NODES + 7) / 8;       // warp per node
    const int d0Blocks   = (N_NODES + D0_NODES - 1) / D0_NODES;

    init_kernel<<<400, 512>>>(basis1, basis_r, loop_r, w_comp);
    hist_kernel<<<800, 256>>>(dst);
    blocksum_kernel<<<NBLK, SCAN_B>>>();
    scanwrite_kernel<<<NBLK, SCAN_B>>>();
    scatter_kernel<<<800, 256>>>(src, dst, etype);

    dense0_kernel<<<d0Blocks, 256>>>(x, loop1, bias);
    fused_kernel<<<warpBlocks, 256>>>(relA, aggA, relB, aggB, s0,
                                      Wf + 0 * 4 * HID * HID, bias + 1 * HID);
    fused_kernel<<<warpBlocks, 256>>>(relB, aggB, relA, aggA, s1,
                                      Wf + 1 * 4 * HID * HID, bias + 2 * HID);
    fused_kernel<<<warpBlocks, 256>>>(relA, aggA, relB, aggB, s2,
                                      Wf + 2 * 4 * HID * HID, bias + 3 * HID);
    final_kernel<<<warpBlocks, 256>>>(relB, aggB, s3);

    pool_kernel<<<(N_NODES + POOL_NODES - 1) / POOL_NODES, 128>>>(gids);
    mlp_kernel<<<N_GRAPH, 64>>>(lin1_w, lin1_b, lin2_w, lin2_b, out);
}

// round 5
// speedup vs baseline: 1.8734x; 1.3337x over previous
#include <cuda_runtime.h>
#include <cuda_fp16.h>
#include <math.h>

#define N_NODES 100000
#define HALF_N  50000
#define IN_DIM  64
#define HID     32
#define N_EDGES 1600000
#define N_GRAPH 256
#define SCAN_B  1024
#define NBLK    ((N_NODES + SCAN_B - 1) / SCAN_B)   // 98
#define WF_BLOCKS 12                                 // 12*1024 = 12288 = 3*4*32*32
#define SCAT_BLOCKS 800
#define D0_NODES 64
#define D0_BLOCKS ((N_NODES + D0_NODES - 1) / D0_NODES)  // 1563

// ---------------- device scratch ----------------
__device__ __half g_relA[(size_t)3 * N_NODES * HID];
__device__ __half g_relB[(size_t)3 * N_NODES * HID];
__device__ float g_aggA[N_NODES * HID];
__device__ float g_aggB[N_NODES * HID];
__device__ float g_s0[N_NODES * HID];
__device__ float g_s1[N_NODES * HID];
__device__ float g_s2[N_NODES * HID];
__device__ float g_s3[N_NODES * HID];
__device__ int   g_deg[N_NODES];
__device__ int   g_cur[N_NODES];
__device__ int   g_rowptr[N_NODES + 1];
__device__ int   g_scanstate[NBLK];             // [31:30]=flag(0 inv,1 agg,2 prefix), [29:0]=val
__device__ int   g_edge_packed[N_EDGES];        // src | (etype<<17)
__device__ float g_Wf[3 * 4 * HID * HID];       // layers 2-4: [layer][rel0..rel2,loop][32][32]
__device__ float g_pooled[N_GRAPH * 128];
__device__ int   g_cnt[N_GRAPH];

__device__ __forceinline__ float fast_tanh(float x) {
    float e = __expf(2.0f * x);
    return 1.0f - __fdividef(2.0f, e + 1.0f);
}

// ---------------- kernel 1: histogram ----------------
__global__ void hist_kernel(const int* __restrict__ dst) {
    const int4* d4 = (const int4*)dst;
    int i = blockIdx.x * blockDim.x + threadIdx.x;
    int stride = gridDim.x * blockDim.x;
    for (int e = i; e < N_EDGES / 4; e += stride) {
        int4 d = __ldg(&d4[e]);
        atomicAdd(&g_deg[d.x], 1);
        atomicAdd(&g_deg[d.y], 1);
        atomicAdd(&g_deg[d.z], 1);
        atomicAdd(&g_deg[d.w], 1);
    }
}

// ---------------- kernel 2: decoupled-lookback scan + Wf combine ----------------
__global__ void scan_kernel(const float* __restrict__ basis_r,
                            const float* __restrict__ loop_r,
                            const float* __restrict__ wcomp) {
    int b = blockIdx.x;
    int t = threadIdx.x, lane = t & 31, wid = t >> 5;

    if (b >= NBLK) {
        // Wf combine: blocks NBLK..NBLK+11
        int j = (b - NBLK) * SCAN_B + t;
        if (j < 3 * 4 * HID * HID) {
            int l  = j / (4 * HID * HID);
            int m  = (j / (HID * HID)) % 4;
            int io = j % (HID * HID);
            if (m < 3)
                g_Wf[j] = wcomp[((l + 1) * 3 + m) * 2 + 0] * basis_r[(l * 2 + 0) * HID * HID + io]
                        + wcomp[((l + 1) * 3 + m) * 2 + 1] * basis_r[(l * 2 + 1) * HID * HID + io];
            else
                g_Wf[j] = loop_r[l * HID * HID + io];
        }
        return;
    }

    __shared__ int ws[32];
    __shared__ int s_exc;
    int i = b * SCAN_B + t;
    int d = (i < N_NODES) ? g_deg[i] : 0;
    int x = d;
    #pragma unroll
    for (int o = 1; o < 32; o <<= 1) {
        int tt = __shfl_up_sync(0xffffffffu, x, o);
        if (lane >= o) x += tt;
    }
    if (lane == 31) ws[wid] = x;
    __syncthreads();
    if (wid == 0) {
        int s = ws[lane];
        #pragma unroll
        for (int o = 1; o < 32; o <<= 1) {
            int tt = __shfl_up_sync(0xffffffffu, s, o);
            if (lane >= o) s += tt;
        }
        ws[lane] = s;
    }
    __syncthreads();
    int total = ws[31];
    int pre = (wid > 0) ? ws[wid - 1] : 0;

    // publish aggregate (or final prefix for block 0)
    if (t == 0) {
        unsigned v = (b == 0) ? ((2u << 30) | (unsigned)total)
                              : ((1u << 30) | (unsigned)total);
        __threadfence();
        atomicExch(&g_scanstate[b], (int)v);
        if (b == 0) s_exc = 0;
    }
    // warp 0 lookback
    if (b > 0 && wid == 0) {
        int excl = 0;
        int look = b - 1;
        while (true) {
            int idx = look - lane;
            unsigned st;
            if (idx >= 0) {
                do { st = (unsigned)atomicAdd(&g_scanstate[idx], 0); } while ((st >> 30) == 0);
            } else {
                st = 0x80000000u;   // flag=2, val=0
            }
            unsigned pf = __ballot_sync(0xffffffffu, (st >> 30) >= 2u);
            int firstp = __ffs(pf) - 1;      // -1 if none
            int v = (int)(st & 0x3FFFFFFFu);
            int take = (firstp < 0) ? v : ((lane <= firstp) ? v : 0);
            #pragma unroll
            for (int o = 16; o > 0; o >>= 1) take += __shfl_down_sync(0xffffffffu, take, o);
            take = __shfl_sync(0xffffffffu, take, 0);
            excl += take;
            if (firstp >= 0) break;
            look -= 32;
        }
        if (lane == 0) {
            atomicExch(&g_scanstate[b], (int)((2u << 30) | (unsigned)(excl + total)));
            s_exc = excl;
        }
    }
    __syncthreads();
    int excl = s_exc + pre + (x - d);
    if (i < N_NODES) { g_rowptr[i] = excl; g_cur[i] = excl; }
    if (b == NBLK - 1 && t == SCAN_B - 1) g_rowptr[N_NODES] = excl + d;
}

// ---------------- kernel 3: scatter + dense0 (merged, independent block ranges) ----------------
__global__ __launch_bounds__(256) void scatter_dense0_kernel(
        const int* __restrict__ src, const int* __restrict__ dst,
        const int* __restrict__ etype,
        const float* __restrict__ x,
        const float* __restrict__ basis1, const float* __restrict__ wcomp,
        const float* __restrict__ loop1, const float* __restrict__ bias) {
    __shared__ float sW[IN_DIM * 128];       // 32KB
    __shared__ float sx[D0_NODES * IN_DIM];  // 16KB
    int t = threadIdx.x;

    if (blockIdx.x < SCAT_BLOCKS) {
        const int4* s4 = (const int4*)src;
        const int4* d4 = (const int4*)dst;
        const int4* t4 = (const int4*)etype;
        int i = blockIdx.x * 256 + t;
        int stride = SCAT_BLOCKS * 256;
        for (int e = i; e < N_EDGES / 4; e += stride) {
            int4 s = __ldg(&s4[e]);
            int4 d = __ldg(&d4[e]);
            int4 r = __ldg(&t4[e]);
            int p;
            p = atomicAdd(&g_cur[d.x], 1); g_edge_packed[p] = s.x | (r.x << 17);
            p = atomicAdd(&g_cur[d.y], 1); g_edge_packed[p] = s.y | (r.y << 17);
            p = atomicAdd(&g_cur[d.z], 1); g_edge_packed[p] = s.z | (r.z << 17);
            p = atomicAdd(&g_cur[d.w], 1); g_edge_packed[p] = s.w | (r.w << 17);
        }
        return;
    }

    // dense0: block handles 64 nodes; self-combined W1 in smem
    int base = (blockIdx.x - SCAT_BLOCKS) * D0_NODES;
    float wc[6];
    #pragma unroll
    for (int q = 0; q < 6; q++) wc[q] = __ldg(&wcomp[q]);   // w_comp[0][r][b]
    for (int j = t; j < IN_DIM * 128; j += 256) {
        int i = j >> 7, f = j & 127;
        int m = f >> 5, c = f & 31;
        if (m < 3)
            sW[j] = wc[m * 2 + 0] * __ldg(&basis1[0 * IN_DIM * HID + i * HID + c])
                  + wc[m * 2 + 1] * __ldg(&basis1[1 * IN_DIM * HID + i * HID + c]);
        else
            sW[j] = __ldg(&loop1[i * HID + c]);
    }
    {
        const float4* x4 = (const float4*)x;
        float4* sx4 = (float4*)sx;
        #pragma unroll
        for (int q = 0; q < 4; q++) {
            int idx = t + 256 * q;
            int node = idx >> 4, f4 = idx & 15;
            int gn = base + node;
            sx4[idx] = (gn < N_NODES) ? __ldg(&x4[gn * 16 + f4])
                                      : make_float4(0.f, 0.f, 0.f, 0.f);
        }
    }
    __syncthreads();
    int ng = t >> 5;
    int f = (t & 31) * 4;
    float acc[8][4];
    #pragma unroll
    for (int j = 0; j < 8; j++) { acc[j][0] = acc[j][1] = acc[j][2] = acc[j][3] = 0.f; }
    #pragma unroll 4
    for (int i = 0; i < IN_DIM; i++) {
        float4 w = *(const float4*)&sW[i * 128 + f];
        #pragma unroll
        for (int j = 0; j < 8; j++) {
            float xv = sx[(ng * 8 + j) * IN_DIM + i];
            acc[j][0] += xv * w.x;
            acc[j][1] += xv * w.y;
            acc[j][2] += xv * w.z;
            acc[j][3] += xv * w.w;
        }
    }
    int m = f >> 5, c = f & 31;
    #pragma unroll
    for (int j = 0; j < 8; j++) {
        int n = base + ng * 8 + j;
        if (n >= N_NODES) break;
        if (m < 3) {
            __half2 ha = __floats2half2_rn(acc[j][0], acc[j][1]);
            __half2 hb = __floats2half2_rn(acc[j][2], acc[j][3]);
            uint2 pk;
            pk.x = *reinterpret_cast<unsigned int*>(&ha);
            pk.y = *reinterpret_cast<unsigned int*>(&hb);
            *(uint2*)&g_relA[((size_t)m * N_NODES + n) * HID + c] = pk;
        } else {
            float4 b4 = *(const float4*)&bias[c];
            *(float4*)&g_aggA[n * HID + c] =
                make_float4(acc[j][0] + b4.x, acc[j][1] + b4.y,
                            acc[j][2] + b4.z, acc[j][3] + b4.w);
        }
    }
}

// ---------------- 2-node gather: broadcast-index, 4 concurrent chains/iter ----------------
__device__ __forceinline__ void gather_pair(const __half* __restrict__ relIn,
                                            int nA, int nB, int m, int c,
                                            float* aA, float* aB) {
    int kA = g_rowptr[nA], dA = g_rowptr[nA + 1] - kA;
    int kB = g_rowptr[nB], dB = g_rowptr[nB + 1] - kB;
    int mx = dA > dB ? dA : dB;
    for (int base = 0; base < mx; base += 8) {
        int e0 = base + m, e1 = base + 4 + m;
        if (e0 < dA) {
            int p = __ldg(&g_edge_packed[kA + e0]);
            uint2 v = __ldg((const uint2*)(relIn + ((size_t)(p >> 17) * N_NODES + (p & 0x1FFFF)) * HID) + c);
            float2 f0 = __half22float2(*(__half2*)&v.x);
            float2 f1 = __half22float2(*(__half2*)&v.y);
            aA[0] += f0.x; aA[1] += f0.y; aA[2] += f1.x; aA[3] += f1.y;
        }
        if (e0 < dB) {
            int p = __ldg(&g_edge_packed[kB + e0]);
            uint2 v = __ldg((const uint2*)(relIn + ((size_t)(p >> 17) * N_NODES + (p & 0x1FFFF)) * HID) + c);
            float2 f0 = __half22float2(*(__half2*)&v.x);
            float2 f1 = __half22float2(*(__half2*)&v.y);
            aB[0] += f0.x; aB[1] += f0.y; aB[2] += f1.x; aB[3] += f1.y;
        }
        if (e1 < dA) {
            int p = __ldg(&g_edge_packed[kA + e1]);
            uint2 v = __ldg((const uint2*)(relIn + ((size_t)(p >> 17) * N_NODES + (p & 0x1FFFF)) * HID) + c);
            float2 f0 = __half22float2(*(__half2*)&v.x);
            float2 f1 = __half22float2(*(__half2*)&v.y);
            aA[0] += f0.x; aA[1] += f0.y; aA[2] += f1.x; aA[3] += f1.y;
        }
        if (e1 < dB) {
            int p = __ldg(&g_edge_packed[kB + e1]);
            uint2 v = __ldg((const uint2*)(relIn + ((size_t)(p >> 17) * N_NODES + (p & 0x1FFFF)) * HID) + c);
            float2 f0 = __half22float2(*(__half2*)&v.x);
            float2 f1 = __half22float2(*(__half2*)&v.y);
            aB[0] += f0.x; aB[1] += f0.y; aB[2] += f1.x; aB[3] += f1.y;
        }
    }
}

// ---------------- kernels 4-6: fused pull + tanh + next-layer dense (2 nodes/warp) ---------
__global__ __launch_bounds__(256) void fused_kernel(const __half* __restrict__ relIn,
                             const float* __restrict__ aggIn,
                             __half* __restrict__ relOut,
                             float* __restrict__ aggOut,
                             float* __restrict__ stateOut,
                             const float* __restrict__ Wf,
                             const float* __restrict__ biasRow)
{
    __shared__ float sW[4 * HID * HID];
    int tid = threadIdx.x;
    for (int i = tid; i < 4 * HID * HID; i += 256) sW[i] = Wf[i];
    __syncthreads();
    int warp = tid >> 5, lane = tid & 31;
    int w = blockIdx.x * 8 + warp;
    int nA = w, nB = w + HALF_N;
    int m = lane >> 3, c = lane & 7;
    float aA[4] = {0.f, 0.f, 0.f, 0.f}, aB[4] = {0.f, 0.f, 0.f, 0.f};
    gather_pair(relIn, nA, nB, m, c, aA, aB);
    #pragma unroll
    for (int o = 8; o <= 16; o <<= 1) {
        #pragma unroll
        for (int q = 0; q < 4; q++) {
            aA[q] += __shfl_xor_sync(0xffffffffu, aA[q], o);
            aB[q] += __shfl_xor_sync(0xffffffffu, aB[q], o);
        }
    }
    float4 slA = ((const float4*)aggIn)[nA * 8 + c];
    float4 slB = ((const float4*)aggIn)[nB * 8 + c];
    float hA[4] = { fast_tanh(aA[0] + slA.x), fast_tanh(aA[1] + slA.y),
                    fast_tanh(aA[2] + slA.z), fast_tanh(aA[3] + slA.w) };
    float hB[4] = { fast_tanh(aB[0] + slB.x), fast_tanh(aB[1] + slB.y),
                    fast_tanh(aB[2] + slB.z), fast_tanh(aB[3] + slB.w) };
    if (m == 0) {
        ((float4*)stateOut)[nA * 8 + c] = make_float4(hA[0], hA[1], hA[2], hA[3]);
        ((float4*)stateOut)[nB * 8 + c] = make_float4(hB[0], hB[1], hB[2], hB[3]);
    }
    int grp = lane & 24;
    float oA[4] = {0.f, 0.f, 0.f, 0.f}, oB[4] = {0.f, 0.f, 0.f, 0.f};
    #pragma unroll
    for (int i = 0; i < 32; i++) {
        float4 wv = *(const float4*)&sW[(m * 32 + i) * 32 + c * 4];
        float hvA = __shfl_sync(0xffffffffu, hA[i & 3], grp | (i >> 2));
        float hvB = __shfl_sync(0xffffffffu, hB[i & 3], grp | (i >> 2));
        oA[0] += hvA * wv.x; oA[1] += hvA * wv.y; oA[2] += hvA * wv.z; oA[3] += hvA * wv.w;
        oB[0] += hvB * wv.x; oB[1] += hvB * wv.y; oB[2] += hvB * wv.z; oB[3] += hvB * wv.w;
    }
    if (m < 3) {
        __half2 ha = __floats2half2_rn(oA[0], oA[1]);
        __half2 hb = __floats2half2_rn(oA[2], oA[3]);
        uint2 pk;
        pk.x = *reinterpret_cast<unsigned int*>(&ha);
        pk.y = *reinterpret_cast<unsigned int*>(&hb);
        ((uint2*)relOut)[((size_t)m * N_NODES + nA) * 8 + c] = pk;
        ha = __floats2half2_rn(oB[0], oB[1]);
        hb = __floats2half2_rn(oB[2], oB[3]);
        pk.x = *reinterpret_cast<unsigned int*>(&ha);
        pk.y = *reinterpret_cast<unsigned int*>(&hb);
        ((uint2*)relOut)[((size_t)m * N_NODES + nB) * 8 + c] = pk;
    } else {
        float4 b4 = ((const float4*)biasRow)[c];
        ((float4*)aggOut)[nA * 8 + c] = make_float4(oA[0] + b4.x, oA[1] + b4.y, oA[2] + b4.z, oA[3] + b4.w);
        ((float4*)aggOut)[nB * 8 + c] = make_float4(oB[0] + b4.x, oB[1] + b4.y, oB[2] + b4.z, oB[3] + b4.w);
    }
}

// ---------------- kernel 7: final pull + tanh ----------------
__global__ __launch_bounds__(256) void final_kernel(const __half* __restrict__ relIn,
                             const float* __restrict__ aggIn,
                             float* __restrict__ stateOut)
{
    int warp = threadIdx.x >> 5, lane = threadIdx.x & 31;
    int w = blockIdx.x * 8 + warp;
    int nA = w, nB = w + HALF_N;
    int m = lane >> 3, c = lane & 7;
    float aA[4] = {0.f, 0.f, 0.f, 0.f}, aB[4] = {0.f, 0.f, 0.f, 0.f};
    gather_pair(relIn, nA, nB, m, c, aA, aB);
    #pragma unroll
    for (int o = 8; o <= 16; o <<= 1) {
        #pragma unroll
        for (int q = 0; q < 4; q++) {
            aA[q] += __shfl_xor_sync(0xffffffffu, aA[q], o);
            aB[q] += __shfl_xor_sync(0xffffffffu, aB[q], o);
        }
    }
    if (m == 0) {
        float4 slA = ((const float4*)aggIn)[nA * 8 + c];
        float4 slB = ((const float4*)aggIn)[nB * 8 + c];
        ((float4*)stateOut)[nA * 8 + c] =
            make_float4(fast_tanh(aA[0] + slA.x), fast_tanh(aA[1] + slA.y),
                        fast_tanh(aA[2] + slA.z), fast_tanh(aA[3] + slA.w));
        ((float4*)stateOut)[nB * 8 + c] =
            make_float4(fast_tanh(aB[0] + slB.x), fast_tanh(aB[1] + slB.y),
                        fast_tanh(aB[2] + slB.z), fast_tanh(aB[3] + slB.w));
    }
}

// ---------------- kernel 8: pooling over sorted graph_ids ----------------
#define POOL_NODES 128
__global__ void pool_kernel(const int* __restrict__ gids) {
    __shared__ int sg[POOL_NODES];
    int f = threadIdx.x;
    int base = blockIdx.x * POOL_NODES;
    {
        int n = base + f;
        sg[f] = (n < N_NODES) ? gids[n] : -1;
    }
    __syncthreads();
    int nn = N_NODES - base;
    if (nn > POOL_NODES) nn = POOL_NODES;
    float acc = 0.f; int curg = -1; int run = 0;
    for (int j = 0; j < nn; j++) {
        int n = base + j;
        float v;
        if (f < 32)       v = g_s0[n * HID + f];
        else if (f < 64)  v = g_s1[n * HID + (f - 32)];
        else if (f < 96)  v = g_s2[n * HID + (f - 64)];
        else              v = g_s3[n * HID + (f - 96)];
        int g = sg[j];
        if (g != curg) {
            if (curg >= 0) {
                atomicAdd(&g_pooled[curg * 128 + f], acc);
                if (f == 0) atomicAdd(&g_cnt[curg], run);
            }
            curg = g; acc = 0.f; run = 0;
        }
        acc += v; run++;
    }
    if (curg >= 0) {
        atomicAdd(&g_pooled[curg * 128 + f], acc);
        if (f == 0) atomicAdd(&g_cnt[curg], run);
    }
}

// ---------------- kernel 9: final MLP ----------------
__global__ void mlp_kernel(const float* __restrict__ lin1_w,
                           const float* __restrict__ lin1_b,
                           const float* __restrict__ lin2_w,
                           const float* __restrict__ lin2_b,
                           float* __restrict__ out) {
    int g = blockIdx.x;
    int k = threadIdx.x;
    __shared__ float sp[128];
    __shared__ float partial[2];
    float cnt = (float)g_cnt[g];
    float inv = 1.0f / fmaxf(cnt, 1.0f);
    sp[k]      = g_pooled[g * 128 + k] * inv;
    sp[64 + k] = g_pooled[g * 128 + 64 + k] * inv;
    __syncthreads();
    float acc = lin1_b[k];
    #pragma unroll
    for (int j = 0; j < 128; j++) acc += sp[j] * lin1_w[j * 64 + k];
    float h = fmaxf(acc, 0.0f);
    float t = h * lin2_w[k];
    #pragma unroll
    for (int o = 16; o > 0; o >>= 1) t += __shfl_down_sync(0xffffffffu, t, o);
    if ((k & 31) == 0) partial[k >> 5] = t;
    __syncthreads();
    if (k == 0) {
        float s = partial[0] + partial[1] + lin2_b[0];
        out[g] = 1.0f / (1.0f + expf(-s));
    }
}

// ---------------- launcher ----------------
extern "C" void kernel_launch(void* const* d_in, const int* in_sizes, int n_in,
                              void* d_out, int out_size) {
    const float* x       = (const float*)d_in[0];
    const float* basis1  = (const float*)d_in[1];
    const float* basis_r = (const float*)d_in[2];
    const float* w_comp  = (const float*)d_in[3];
    const float* loop1   = (const float*)d_in[4];
    const float* loop_r  = (const float*)d_in[5];
    const float* bias    = (const float*)d_in[6];
    const float* lin1_w  = (const float*)d_in[7];
    const float* lin1_b  = (const float*)d_in[8];
    const float* lin2_w  = (const float*)d_in[9];
    const float* lin2_b  = (const float*)d_in[10];
    const int*   src     = (const int*)d_in[11];
    const int*   dst     = (const int*)d_in[12];
    const int*   etype   = (const int*)d_in[13];
    const int*   gids    = (const int*)d_in[14];
    float* out = (float*)d_out;

    __half *relA, *relB;
    float *aggA, *aggB, *s0, *s1, *s2, *s3, *Wf, *pooled;
    int *deg, *scanstate, *cnt;
    cudaGetSymbolAddress((void**)&relA, g_relA);
    cudaGetSymbolAddress((void**)&relB, g_relB);
    cudaGetSymbolAddress((void**)&aggA, g_aggA);
    cudaGetSymbolAddress((void**)&aggB, g_aggB);
    cudaGetSymbolAddress((void**)&s0, g_s0);
    cudaGetSymbolAddress((void**)&s1, g_s1);
    cudaGetSymbolAddress((void**)&s2, g_s2);
    cudaGetSymbolAddress((void**)&s3, g_s3);
    cudaGetSymbolAddress((void**)&Wf, g_Wf);
    cudaGetSymbolAddress((void**)&pooled, g_pooled);
    cudaGetSymbolAddress((void**)&deg, g_deg);
    cudaGetSymbolAddress((void**)&scanstate, g_scanstate);
    cudaGetSymbolAddress((void**)&cnt, g_cnt);

    // memset nodes (not kernel launches)
    cudaMemsetAsync(deg, 0, N_NODES * sizeof(int));
    cudaMemsetAsync(scanstate, 0, NBLK * sizeof(int));
    cudaMemsetAsync(pooled, 0, N_GRAPH * 128 * sizeof(float));
    cudaMemsetAsync(cnt, 0, N_GRAPH * sizeof(int));

    const int fusedBlocks = HALF_N / 8;             // 6250, 2 nodes per warp

    // 1
    hist_kernel<<<800, 256>>>(dst);
    // 2
    scan_kernel<<<NBLK + WF_BLOCKS, SCAN_B>>>(basis_r, loop_r, w_comp);
    // 3
    scatter_dense0_kernel<<<SCAT_BLOCKS + D0_BLOCKS, 256>>>(src, dst, etype, x,
                                                            basis1, w_comp, loop1, bias);
    // 4 (profiled by ncu)
    fused_kernel<<<fusedBlocks, 256>>>(relA, aggA, relB, aggB, s0,
                                       Wf + 0 * 4 * HID * HID, bias + 1 * HID);
    // 5
    fused_kernel<<<fusedBlocks, 256>>>(relB, aggB, relA, aggA, s1,
                                       Wf + 1 * 4 * HID * HID, bias + 2 * HID);
    // 6
    fused_kernel<<<fusedBlocks, 256>>>(relA, aggA, relB, aggB, s2,
                                       Wf + 2 * 4 * HID * HID, bias + 3 * HID);
    // 7
    final_kernel<<<fusedBlocks, 256>>>(relB, aggB, s3);
    // 8
    pool_kernel<<<(N_NODES + POOL_NODES - 1) / POOL_NODES, 128>>>(gids);
    // 9
    mlp_kernel<<<N_GRAPH, 64>>>(lin1_w, lin1_b, lin2_w, lin2_b, out);
}